// round 1
// baseline (speedup 1.0000x reference)
#include <cuda_runtime.h>
#include <math.h>

// Problem constants
#define Bv  4
#define Tv  2048
#define Ev  1024
#define Hv  16
#define Dv  64
#define HDv 1024      // H*D
#define BTv 8192      // B*T
#define BHv 64        // B*H

// -------- scratch (device globals; no runtime allocation) --------
static __device__ float g_Q[(size_t)BHv * Tv * Dv];          // [b,h,t,d]
static __device__ float g_K[(size_t)BHv * Tv * Dv];
static __device__ float g_V[(size_t)BHv * Tv * Dv];
static __device__ float g_S[(size_t)BHv * Tv * Tv];          // scores -> probs (1 GiB)
static __device__ float g_M[BHv * Tv];                       // row max
static __device__ float g_L[BHv * Tv];                       // row sumexp
static __device__ float g_AV[(size_t)BTv * HDv];             // attn output, [b,t,h*D+d]

// ============================================================================
// NT GEMM: C[M,N] = alpha * A * B^T.  A:[M,K] ld=K, B:[N,K] ld=K.
// 128x128 block tile, 256 threads, 8x8 microtile, k-tile 8.
// MODE 0: plain row-major C (ldc = N), batched via blockIdx.z strides.
// MODE 1: projection store: row=(b,t), col=(h,d) -> C[((b*H+h)*T+t)*D+d]
// ============================================================================
template <int MODE>
__global__ void __launch_bounds__(256)
gemm_nt(const float* __restrict__ A, const float* __restrict__ Bm,
        float* __restrict__ C, int M, int N, int K,
        size_t sA, size_t sB, size_t sC, float alpha)
{
    __shared__ float As[8][132];
    __shared__ float Bs[8][132];

    const int tid = threadIdx.x;
    const int tx  = tid & 15;      // 0..15 -> col = tx*8
    const int ty  = tid >> 4;      // 0..15 -> row = ty*8
    const int lr  = tid >> 1;      // 0..127: tile row loaded by this thread
    const int lk  = (tid & 1) * 4; // 0 or 4: k offset (float4)

    const float* Ab = A + blockIdx.z * sA + (size_t)(blockIdx.y * 128 + lr) * K + lk;
    const float* Bb = Bm + blockIdx.z * sB + (size_t)(blockIdx.x * 128 + lr) * K + lk;

    float acc[8][8];
#pragma unroll
    for (int i = 0; i < 8; i++)
#pragma unroll
        for (int j = 0; j < 8; j++) acc[i][j] = 0.0f;

    for (int k0 = 0; k0 < K; k0 += 8) {
        float4 a4 = *(const float4*)(Ab + k0);
        float4 b4 = *(const float4*)(Bb + k0);
        __syncthreads();
        As[lk + 0][lr] = a4.x; As[lk + 1][lr] = a4.y;
        As[lk + 2][lr] = a4.z; As[lk + 3][lr] = a4.w;
        Bs[lk + 0][lr] = b4.x; Bs[lk + 1][lr] = b4.y;
        Bs[lk + 2][lr] = b4.z; Bs[lk + 3][lr] = b4.w;
        __syncthreads();
#pragma unroll
        for (int kk = 0; kk < 8; kk++) {
            float ra[8], rb[8];
            *(float4*)(ra)     = *(const float4*)(&As[kk][ty * 8]);
            *(float4*)(ra + 4) = *(const float4*)(&As[kk][ty * 8 + 4]);
            *(float4*)(rb)     = *(const float4*)(&Bs[kk][tx * 8]);
            *(float4*)(rb + 4) = *(const float4*)(&Bs[kk][tx * 8 + 4]);
#pragma unroll
            for (int i = 0; i < 8; i++)
#pragma unroll
                for (int j = 0; j < 8; j++)
                    acc[i][j] += ra[i] * rb[j];
        }
    }

    const int row0 = blockIdx.y * 128 + ty * 8;
    const int col0 = blockIdx.x * 128 + tx * 8;

    if (MODE == 0) {
        float* Cb = C + blockIdx.z * sC;
#pragma unroll
        for (int i = 0; i < 8; i++) {
            float4 o0 = make_float4(acc[i][0] * alpha, acc[i][1] * alpha,
                                    acc[i][2] * alpha, acc[i][3] * alpha);
            float4 o1 = make_float4(acc[i][4] * alpha, acc[i][5] * alpha,
                                    acc[i][6] * alpha, acc[i][7] * alpha);
            *(float4*)(&Cb[(size_t)(row0 + i) * N + col0])     = o0;
            *(float4*)(&Cb[(size_t)(row0 + i) * N + col0 + 4]) = o1;
        }
    } else {
        // QKV projection store: row -> (b,t), col -> (h,d)
        const int h = col0 >> 6;     // col0 multiple of 8, so quads stay in-head
        const int d = col0 & 63;
#pragma unroll
        for (int i = 0; i < 8; i++) {
            int row = row0 + i;
            int b = row >> 11;       // /T (2048)
            int t = row & 2047;
            float* dst = C + ((size_t)(b * Hv + h) * Tv + t) * Dv + d;
            *(float4*)(dst)     = make_float4(acc[i][0], acc[i][1], acc[i][2], acc[i][3]);
            *(float4*)(dst + 4) = make_float4(acc[i][4], acc[i][5], acc[i][6], acc[i][7]);
        }
    }
}

// ============================================================================
// P @ V GEMM: per (b,h): AV_part[t,d] = sum_s P[t,s] * V[s,d]
// 128x64 block tile, 256 threads, 8x4 microtile, k-tile 8.
// Fused store into g_AV layout [b, t, h*D + d].
// ============================================================================
__global__ void __launch_bounds__(256)
pv_gemm(const float* __restrict__ P, const float* __restrict__ V,
        float* __restrict__ AV)
{
    __shared__ float As[8][132];
    __shared__ float Bs[8][68];

    const int tid = threadIdx.x;
    const int tx  = tid & 15;      // col = tx*4
    const int ty  = tid >> 4;      // row = ty*8
    const int lr  = tid >> 1;
    const int lk  = (tid & 1) * 4;
    const int bh  = blockIdx.z;

    const float* Pb = P + (size_t)bh * Tv * Tv + (size_t)(blockIdx.y * 128 + lr) * Tv + lk;
    const float* Vb = V + (size_t)bh * Tv * Dv;

    float acc[8][4];
#pragma unroll
    for (int i = 0; i < 8; i++)
#pragma unroll
        for (int j = 0; j < 4; j++) acc[i][j] = 0.0f;

    const int bkk = tid >> 4;          // 0..15 (only tid<128 used)
    const int bn4 = (tid & 15) * 4;

    for (int k0 = 0; k0 < Tv; k0 += 8) {
        float4 a4 = *(const float4*)(Pb + k0);
        float4 b4 = make_float4(0.f, 0.f, 0.f, 0.f);
        if (tid < 128)
            b4 = *(const float4*)(Vb + (size_t)(k0 + bkk) * Dv + bn4);
        __syncthreads();
        As[lk + 0][lr] = a4.x; As[lk + 1][lr] = a4.y;
        As[lk + 2][lr] = a4.z; As[lk + 3][lr] = a4.w;
        if (tid < 128) {
            Bs[bkk][bn4 + 0] = b4.x; Bs[bkk][bn4 + 1] = b4.y;
            Bs[bkk][bn4 + 2] = b4.z; Bs[bkk][bn4 + 3] = b4.w;
        }
        __syncthreads();
#pragma unroll
        for (int kk = 0; kk < 8; kk++) {
            float ra[8], rb[4];
            *(float4*)(ra)     = *(const float4*)(&As[kk][ty * 8]);
            *(float4*)(ra + 4) = *(const float4*)(&As[kk][ty * 8 + 4]);
            *(float4*)(rb)     = *(const float4*)(&Bs[kk][tx * 4]);
#pragma unroll
            for (int i = 0; i < 8; i++)
#pragma unroll
                for (int j = 0; j < 4; j++)
                    acc[i][j] += ra[i] * rb[j];
        }
    }

    const int b = bh / Hv, h = bh % Hv;
    const int row0 = blockIdx.y * 128 + ty * 8;
    const int col  = tx * 4;
#pragma unroll
    for (int i = 0; i < 8; i++) {
        int t = row0 + i;
        *(float4*)(AV + ((size_t)b * Tv + t) * HDv + h * Dv + col) =
            make_float4(acc[i][0], acc[i][1], acc[i][2], acc[i][3]);
    }
}

// ============================================================================
// Row stats: one block per (bh, t) row of S; single HBM pass (row in regs).
// ============================================================================
__global__ void __launch_bounds__(256)
rowstats(const float* __restrict__ S, float* __restrict__ Mv, float* __restrict__ Lv)
{
    __shared__ float red[256];
    const size_t row = blockIdx.x;
    const float* p = S + row * Tv;
    const int tid = threadIdx.x;

    float v[8];
    float m = -1e30f;
#pragma unroll
    for (int i = 0; i < 8; i++) { v[i] = p[tid + i * 256]; m = fmaxf(m, v[i]); }
    red[tid] = m; __syncthreads();
    for (int o = 128; o > 0; o >>= 1) {
        if (tid < o) red[tid] = fmaxf(red[tid], red[tid + o]);
        __syncthreads();
    }
    m = red[0];
    __syncthreads();
    float l = 0.0f;
#pragma unroll
    for (int i = 0; i < 8; i++) l += expf(v[i] - m);
    red[tid] = l; __syncthreads();
    for (int o = 128; o > 0; o >>= 1) {
        if (tid < o) red[tid] += red[tid + o];
        __syncthreads();
    }
    if (tid == 0) { Mv[row] = m; Lv[row] = red[0]; }
}

// ============================================================================
// Normalize S -> P in place + accumulate head mean into d_out region 2.
// grid: (T/512, T, B); block handles 512 s-positions of one (b,t), all 16 h.
// ============================================================================
__global__ void __launch_bounds__(256)
norm_mean(float* __restrict__ S, const float* __restrict__ Mv,
          const float* __restrict__ Lv, float* __restrict__ meanout)
{
    const int b = blockIdx.z, t = blockIdx.y;
    const int s0 = blockIdx.x * 512;
    const int tid = threadIdx.x;

    __shared__ float sm[16], sl[16];
    if (tid < 16) {
        int idx = (b * Hv + tid) * Tv + t;
        sm[tid] = Mv[idx];
        sl[tid] = 1.0f / Lv[idx];
    }
    __syncthreads();

    const int s1 = s0 + tid;
    const int s2 = s1 + 256;
    float a0 = 0.0f, a1 = 0.0f;
    for (int h = 0; h < Hv; h++) {
        size_t base = ((size_t)(b * Hv + h) * Tv + t) * Tv;
        float p0 = expf(S[base + s1] - sm[h]) * sl[h];
        float p1 = expf(S[base + s2] - sm[h]) * sl[h];
        S[base + s1] = p0;
        S[base + s2] = p1;
        a0 += p0;
        a1 += p1;
    }
    const size_t mb = ((size_t)b * Tv + t) * Tv;
    meanout[mb + s1] = a0 * (1.0f / Hv);
    meanout[mb + s2] = a1 * (1.0f / Hv);
}

// ============================================================================
// Launch
// ============================================================================
extern "C" void kernel_launch(void* const* d_in, const int* in_sizes, int n_in,
                              void* d_out, int out_size)
{
    const float* q  = (const float*)d_in[0];
    const float* k  = (const float*)d_in[1];
    const float* v  = (const float*)d_in[2];
    const float* Wq = (const float*)d_in[3];
    const float* Wk = (const float*)d_in[4];
    const float* Wv = (const float*)d_in[5];
    const float* Wo = (const float*)d_in[6];

    float* xout    = (float*)d_out;                                        // [B,T,E]
    float* meanout = (float*)d_out + ((size_t)out_size - (size_t)Bv * Tv * Tv); // [B,T,T]

    float *pQ, *pK, *pV, *pS, *pM, *pL, *pAV;
    cudaGetSymbolAddress((void**)&pQ,  g_Q);
    cudaGetSymbolAddress((void**)&pK,  g_K);
    cudaGetSymbolAddress((void**)&pV,  g_V);
    cudaGetSymbolAddress((void**)&pS,  g_S);
    cudaGetSymbolAddress((void**)&pM,  g_M);
    cudaGetSymbolAddress((void**)&pL,  g_L);
    cudaGetSymbolAddress((void**)&pAV, g_AV);

    dim3 thr(256);

    // 1) Projections: [BT,E] @ W^T -> [b,h,t,d]
    dim3 gProj(HDv / 128, BTv / 128, 1);
    gemm_nt<1><<<gProj, thr>>>(q, Wq, pQ, BTv, HDv, Ev, 0, 0, 0, 1.0f);
    gemm_nt<1><<<gProj, thr>>>(k, Wk, pK, BTv, HDv, Ev, 0, 0, 0, 1.0f);
    gemm_nt<1><<<gProj, thr>>>(v, Wv, pV, BTv, HDv, Ev, 0, 0, 0, 1.0f);

    // 2) Scores: per (b,h), S = Q K^T / sqrt(D)
    dim3 gScore(Tv / 128, Tv / 128, BHv);
    gemm_nt<0><<<gScore, thr>>>(pQ, pK, pS, Tv, Tv, Dv,
                                (size_t)Tv * Dv, (size_t)Tv * Dv,
                                (size_t)Tv * Tv, 0.125f);

    // 3) Softmax stats, then normalize + head-mean output
    rowstats<<<BHv * Tv, 256>>>(pS, pM, pL);
    norm_mean<<<dim3(Tv / 512, Tv, Bv), 256>>>(pS, pM, pL, meanout);

    // 4) attn @ V -> g_AV [b,t,h*D]
    pv_gemm<<<dim3(1, Tv / 128, BHv), 256>>>(pS, pV, pAV);

    // 5) Output projection: [BT,HD] @ Wo^T -> x
    dim3 gOut(Ev / 128, BTv / 128, 1);
    gemm_nt<0><<<gOut, thr>>>(pAV, Wo, xout, BTv, Ev, HDv, 0, 0, 0, 1.0f);
}

// round 2
// speedup vs baseline: 1.1307x; 1.1307x over previous
#include <cuda_runtime.h>
#include <math.h>

// Problem constants
#define Bv  4
#define Tv  2048
#define Ev  1024
#define Hv  16
#define Dv  64
#define HDv 1024      // H*D
#define BTv 8192      // B*T
#define BHv 64        // B*H

// -------- scratch (device globals; no runtime allocation) --------
static __device__ float g_Q[(size_t)BHv * Tv * Dv];          // [b,h,t,d]
static __device__ float g_K[(size_t)BHv * Tv * Dv];
static __device__ float g_V[(size_t)BHv * Tv * Dv];
static __device__ float g_S[(size_t)BHv * Tv * Tv];          // raw scores (1 GiB)
static __device__ float g_M[BHv * Tv];                       // row max
static __device__ float g_Linv[BHv * Tv];                    // 1 / row sumexp
static __device__ float g_AV[(size_t)BTv * HDv];             // attn output, [b,t,h*D+d]

// ============================================================================
// NT GEMM: C[M,N] = alpha * A * B^T.  A:[M,K] ld=K, B:[N,K] ld=K.
// 128x128 block tile, 256 threads, 8x8 microtile, k-tile 8.
// MODE 0: plain row-major C (ldc = N), batched via blockIdx.z strides.
// MODE 1: projection store: row=(b,t), col=(h,d) -> C[((b*H+h)*T+t)*D+d]
// ============================================================================
template <int MODE>
__global__ void __launch_bounds__(256)
gemm_nt(const float* __restrict__ A, const float* __restrict__ Bm,
        float* __restrict__ C, int M, int N, int K,
        size_t sA, size_t sB, size_t sC, float alpha)
{
    __shared__ float As[8][132];
    __shared__ float Bs[8][132];

    const int tid = threadIdx.x;
    const int tx  = tid & 15;      // 0..15 -> col = tx*8
    const int ty  = tid >> 4;      // 0..15 -> row = ty*8
    const int lr  = tid >> 1;      // 0..127: tile row loaded by this thread
    const int lk  = (tid & 1) * 4; // 0 or 4: k offset (float4)

    const float* Ab = A + blockIdx.z * sA + (size_t)(blockIdx.y * 128 + lr) * K + lk;
    const float* Bb = Bm + blockIdx.z * sB + (size_t)(blockIdx.x * 128 + lr) * K + lk;

    float acc[8][8];
#pragma unroll
    for (int i = 0; i < 8; i++)
#pragma unroll
        for (int j = 0; j < 8; j++) acc[i][j] = 0.0f;

    for (int k0 = 0; k0 < K; k0 += 8) {
        float4 a4 = *(const float4*)(Ab + k0);
        float4 b4 = *(const float4*)(Bb + k0);
        __syncthreads();
        As[lk + 0][lr] = a4.x; As[lk + 1][lr] = a4.y;
        As[lk + 2][lr] = a4.z; As[lk + 3][lr] = a4.w;
        Bs[lk + 0][lr] = b4.x; Bs[lk + 1][lr] = b4.y;
        Bs[lk + 2][lr] = b4.z; Bs[lk + 3][lr] = b4.w;
        __syncthreads();
#pragma unroll
        for (int kk = 0; kk < 8; kk++) {
            float ra[8], rb[8];
            *(float4*)(ra)     = *(const float4*)(&As[kk][ty * 8]);
            *(float4*)(ra + 4) = *(const float4*)(&As[kk][ty * 8 + 4]);
            *(float4*)(rb)     = *(const float4*)(&Bs[kk][tx * 8]);
            *(float4*)(rb + 4) = *(const float4*)(&Bs[kk][tx * 8 + 4]);
#pragma unroll
            for (int i = 0; i < 8; i++)
#pragma unroll
                for (int j = 0; j < 8; j++)
                    acc[i][j] += ra[i] * rb[j];
        }
    }

    const int row0 = blockIdx.y * 128 + ty * 8;
    const int col0 = blockIdx.x * 128 + tx * 8;

    if (MODE == 0) {
        float* Cb = C + blockIdx.z * sC;
#pragma unroll
        for (int i = 0; i < 8; i++) {
            float4 o0 = make_float4(acc[i][0] * alpha, acc[i][1] * alpha,
                                    acc[i][2] * alpha, acc[i][3] * alpha);
            float4 o1 = make_float4(acc[i][4] * alpha, acc[i][5] * alpha,
                                    acc[i][6] * alpha, acc[i][7] * alpha);
            *(float4*)(&Cb[(size_t)(row0 + i) * N + col0])     = o0;
            *(float4*)(&Cb[(size_t)(row0 + i) * N + col0 + 4]) = o1;
        }
    } else {
        // QKV projection store: row -> (b,t), col -> (h,d)
        const int h = col0 >> 6;     // col0 multiple of 8, so quads stay in-head
        const int d = col0 & 63;
#pragma unroll
        for (int i = 0; i < 8; i++) {
            int row = row0 + i;
            int b = row >> 11;       // /T (2048)
            int t = row & 2047;
            float* dst = C + ((size_t)(b * Hv + h) * Tv + t) * Dv + d;
            *(float4*)(dst)     = make_float4(acc[i][0], acc[i][1], acc[i][2], acc[i][3]);
            *(float4*)(dst + 4) = make_float4(acc[i][4], acc[i][5], acc[i][6], acc[i][7]);
        }
    }
}

// ============================================================================
// Fused softmax stats + head-mean output.
// One block per (b,t). Loops over the 16 heads; each head's 2048-wide row of
// raw scores lives in registers (8 per thread). Computes row max m, sumexp l,
// writes m and 1/l for pv_gemm, and accumulates mean_h p directly to d_out.
// S is read exactly once; never written.
// ============================================================================
__global__ void __launch_bounds__(256)
stats_mean(const float* __restrict__ S, float* __restrict__ Mv,
           float* __restrict__ Linv, float* __restrict__ meanout)
{
    const int bt  = blockIdx.x;
    const int b   = bt >> 11;
    const int t   = bt & 2047;
    const int tid = threadIdx.x;
    const int lane = tid & 31;
    const int wid  = tid >> 5;

    __shared__ float red[8];

    float acc[8];
#pragma unroll
    for (int i = 0; i < 8; i++) acc[i] = 0.0f;

    for (int h = 0; h < Hv; h++) {
        const size_t base = ((size_t)(b * Hv + h) * Tv + t) * Tv;
        float v[8];
#pragma unroll
        for (int i = 0; i < 8; i++) v[i] = S[base + tid + i * 256];

        // --- row max ---
        float m = v[0];
#pragma unroll
        for (int i = 1; i < 8; i++) m = fmaxf(m, v[i]);
#pragma unroll
        for (int o = 16; o > 0; o >>= 1)
            m = fmaxf(m, __shfl_xor_sync(0xffffffffu, m, o));
        if (lane == 0) red[wid] = m;
        __syncthreads();
        m = red[0];
#pragma unroll
        for (int i = 1; i < 8; i++) m = fmaxf(m, red[i]);

        // --- sumexp ---
        float e[8];
        float l = 0.0f;
#pragma unroll
        for (int i = 0; i < 8; i++) { e[i] = __expf(v[i] - m); l += e[i]; }
#pragma unroll
        for (int o = 16; o > 0; o >>= 1)
            l += __shfl_xor_sync(0xffffffffu, l, o);
        __syncthreads();             // everyone done reading max values
        if (lane == 0) red[wid] = l;
        __syncthreads();
        l = red[0];
#pragma unroll
        for (int i = 1; i < 8; i++) l += red[i];
        const float linv = 1.0f / l;

        if (tid == 0) {
            Mv[(b * Hv + h) * Tv + t]   = m;
            Linv[(b * Hv + h) * Tv + t] = linv;
        }
#pragma unroll
        for (int i = 0; i < 8; i++) acc[i] += e[i] * linv;
        __syncthreads();             // red reusable next head
    }

    const size_t mb = (size_t)bt * Tv;
#pragma unroll
    for (int i = 0; i < 8; i++)
        meanout[mb + tid + i * 256] = acc[i] * (1.0f / Hv);
}

// ============================================================================
// P @ V GEMM with softmax fused into the A-tile load:
//   p[t,s] = __expf(S[t,s] - m[t]) * linv[t]
// per (b,h): AV_part[t,d] = sum_s p[t,s] * V[s,d]
// 128x64 block tile, 256 threads, 8x4 microtile, k-tile 8.
// Fused store into g_AV layout [b, t, h*D + d].
// ============================================================================
__global__ void __launch_bounds__(256)
pv_gemm(const float* __restrict__ S, const float* __restrict__ V,
        const float* __restrict__ Mv, const float* __restrict__ Linv,
        float* __restrict__ AV)
{
    __shared__ float As[8][132];
    __shared__ float Bs[8][68];

    const int tid = threadIdx.x;
    const int tx  = tid & 15;      // col = tx*4
    const int ty  = tid >> 4;      // row = ty*8
    const int lr  = tid >> 1;
    const int lk  = (tid & 1) * 4;
    const int bh  = blockIdx.z;

    const int arow = blockIdx.y * 128 + lr;
    const float mrow = Mv[bh * Tv + arow];
    const float lrow = Linv[bh * Tv + arow];

    const float* Pb = S + (size_t)bh * Tv * Tv + (size_t)arow * Tv + lk;
    const float* Vb = V + (size_t)bh * Tv * Dv;

    float acc[8][4];
#pragma unroll
    for (int i = 0; i < 8; i++)
#pragma unroll
        for (int j = 0; j < 4; j++) acc[i][j] = 0.0f;

    const int bkk = tid >> 4;          // 0..15 (only tid<128 used)
    const int bn4 = (tid & 15) * 4;

    for (int k0 = 0; k0 < Tv; k0 += 8) {
        float4 a4 = *(const float4*)(Pb + k0);
        float4 b4 = make_float4(0.f, 0.f, 0.f, 0.f);
        if (tid < 128)
            b4 = *(const float4*)(Vb + (size_t)(k0 + bkk) * Dv + bn4);
        __syncthreads();
        As[lk + 0][lr] = __expf(a4.x - mrow) * lrow;
        As[lk + 1][lr] = __expf(a4.y - mrow) * lrow;
        As[lk + 2][lr] = __expf(a4.z - mrow) * lrow;
        As[lk + 3][lr] = __expf(a4.w - mrow) * lrow;
        if (tid < 128) {
            Bs[bkk][bn4 + 0] = b4.x; Bs[bkk][bn4 + 1] = b4.y;
            Bs[bkk][bn4 + 2] = b4.z; Bs[bkk][bn4 + 3] = b4.w;
        }
        __syncthreads();
#pragma unroll
        for (int kk = 0; kk < 8; kk++) {
            float ra[8], rb[4];
            *(float4*)(ra)     = *(const float4*)(&As[kk][ty * 8]);
            *(float4*)(ra + 4) = *(const float4*)(&As[kk][ty * 8 + 4]);
            *(float4*)(rb)     = *(const float4*)(&Bs[kk][tx * 4]);
#pragma unroll
            for (int i = 0; i < 8; i++)
#pragma unroll
                for (int j = 0; j < 4; j++)
                    acc[i][j] += ra[i] * rb[j];
        }
    }

    const int b = bh / Hv, h = bh % Hv;
    const int row0 = blockIdx.y * 128 + ty * 8;
    const int col  = tx * 4;
#pragma unroll
    for (int i = 0; i < 8; i++) {
        int t = row0 + i;
        *(float4*)(AV + ((size_t)b * Tv + t) * HDv + h * Dv + col) =
            make_float4(acc[i][0], acc[i][1], acc[i][2], acc[i][3]);
    }
}

// ============================================================================
// Launch
// ============================================================================
extern "C" void kernel_launch(void* const* d_in, const int* in_sizes, int n_in,
                              void* d_out, int out_size)
{
    const float* q  = (const float*)d_in[0];
    const float* k  = (const float*)d_in[1];
    const float* v  = (const float*)d_in[2];
    const float* Wq = (const float*)d_in[3];
    const float* Wk = (const float*)d_in[4];
    const float* Wv = (const float*)d_in[5];
    const float* Wo = (const float*)d_in[6];

    float* xout    = (float*)d_out;                                        // [B,T,E]
    float* meanout = (float*)d_out + ((size_t)out_size - (size_t)Bv * Tv * Tv); // [B,T,T]

    float *pQ, *pK, *pV, *pS, *pM, *pL, *pAV;
    cudaGetSymbolAddress((void**)&pQ,  g_Q);
    cudaGetSymbolAddress((void**)&pK,  g_K);
    cudaGetSymbolAddress((void**)&pV,  g_V);
    cudaGetSymbolAddress((void**)&pS,  g_S);
    cudaGetSymbolAddress((void**)&pM,  g_M);
    cudaGetSymbolAddress((void**)&pL,  g_Linv);
    cudaGetSymbolAddress((void**)&pAV, g_AV);

    dim3 thr(256);

    // 1) Projections: [BT,E] @ W^T -> [b,h,t,d]
    dim3 gProj(HDv / 128, BTv / 128, 1);
    gemm_nt<1><<<gProj, thr>>>(q, Wq, pQ, BTv, HDv, Ev, 0, 0, 0, 1.0f);
    gemm_nt<1><<<gProj, thr>>>(k, Wk, pK, BTv, HDv, Ev, 0, 0, 0, 1.0f);
    gemm_nt<1><<<gProj, thr>>>(v, Wv, pV, BTv, HDv, Ev, 0, 0, 0, 1.0f);

    // 2) Scores: per (b,h), S = Q K^T / sqrt(D)  (raw scores, written once)
    dim3 gScore(Tv / 128, Tv / 128, BHv);
    gemm_nt<0><<<gScore, thr>>>(pQ, pK, pS, Tv, Tv, Dv,
                                (size_t)Tv * Dv, (size_t)Tv * Dv,
                                (size_t)Tv * Tv, 0.125f);

    // 3) Fused softmax stats + head-mean (reads S once, writes mean to d_out)
    stats_mean<<<BTv, 256>>>(pS, pM, pL, meanout);

    // 4) attn @ V with fused normalization -> g_AV [b,t,h*D]
    pv_gemm<<<dim3(1, Tv / 128, BHv), 256>>>(pS, pV, pM, pL, pAV);

    // 5) Output projection: [BT,HD] @ Wo^T -> x
    dim3 gOut(Ev / 128, BTv / 128, 1);
    gemm_nt<0><<<gOut, thr>>>(pAV, Wo, xout, BTv, Ev, HDv, 0, 0, 0, 1.0f);
}

// round 3
// speedup vs baseline: 1.3152x; 1.1631x over previous
#include <cuda_runtime.h>
#include <math.h>
#include <stdint.h>

// Problem constants
#define Bv  4
#define Tv  2048
#define Ev  1024
#define Hv  16
#define Dv  64
#define HDv 1024      // H*D
#define BTv 8192      // B*T
#define BHv 64        // B*H

// -------- scratch (device globals; no runtime allocation) --------
static __device__ float g_Q[(size_t)BHv * Tv * Dv];          // [b,h,t,d]
static __device__ float g_K[(size_t)BHv * Tv * Dv];
static __device__ float g_V[(size_t)BHv * Tv * Dv];
static __device__ float g_S[(size_t)BHv * Tv * Tv];          // raw scores (1 GiB)
static __device__ float g_M[BHv * Tv];                       // row max
static __device__ float g_Linv[BHv * Tv];                    // 1 / row sumexp
static __device__ float g_AV[(size_t)BTv * HDv];             // attn out, [b,t,h*D+d]

// ---------------- tf32 helpers ----------------
__device__ __forceinline__ uint32_t f2tf32(float f) {
    uint32_t u;
    asm("cvt.rna.tf32.f32 %0, %1;" : "=r"(u) : "f"(f));
    return u;
}

__device__ __forceinline__ void mma_tf32(float c[4],
        uint32_t a0, uint32_t a1, uint32_t a2, uint32_t a3,
        uint32_t b0, uint32_t b1)
{
    asm volatile(
        "mma.sync.aligned.m16n8k8.row.col.f32.tf32.tf32.f32 "
        "{%0,%1,%2,%3}, {%4,%5,%6,%7}, {%8,%9}, {%0,%1,%2,%3};"
        : "+f"(c[0]), "+f"(c[1]), "+f"(c[2]), "+f"(c[3])
        : "r"(a0), "r"(a1), "r"(a2), "r"(a3), "r"(b0), "r"(b1));
}

// ============================================================================
// Tensor-core NT GEMM: C[M,N] = alpha * A * B^T.  A:[M,K] ld=K, B:[N,K] ld=K.
// 128x128 block tile, 256 threads (8 warps, 2Mx4N), warp tile 64x32,
// m16n8k8 tf32 mma, BK=16 (2 k-steps per shared tile).
// MODE 0: row-major C (ldc=N), batched via blockIdx.z strides, scaled by alpha
// MODE 1: projection store: row=(b,t), col=(h,d) -> C[((b*H+h)*T+t)*D+d]
// ============================================================================
template <int MODE>
__global__ void __launch_bounds__(256)
gemm_nt_tc(const float* __restrict__ A, const float* __restrict__ Bm,
           float* __restrict__ C, int M, int N, int K,
           size_t sA, size_t sB, size_t sC, float alpha)
{
    __shared__ uint32_t As[16][133];   // [k][m]
    __shared__ uint32_t Bs[16][133];   // [k][n]

    const int tid  = threadIdx.x;
    const int lane = tid & 31;
    const int w    = tid >> 5;
    const int gid  = lane >> 2;     // 0..7
    const int tig  = lane & 3;      // 0..3
    const int wm   = (w & 1) * 64;  // warp M offset in tile
    const int wn   = (w >> 1) * 32; // warp N offset in tile

    const int lrow = tid >> 1;          // 0..127
    const int lko  = (tid & 1) * 8;     // 0 or 8

    const float* Ab = A + blockIdx.z * sA + (size_t)(blockIdx.y * 128 + lrow) * K + lko;
    const float* Bb = Bm + blockIdx.z * sB + (size_t)(blockIdx.x * 128 + lrow) * K + lko;

    float acc[4][4][4];
#pragma unroll
    for (int mt = 0; mt < 4; mt++)
#pragma unroll
        for (int nt = 0; nt < 4; nt++)
#pragma unroll
            for (int i = 0; i < 4; i++) acc[mt][nt][i] = 0.0f;

    for (int k0 = 0; k0 < K; k0 += 16) {
        float4 av0 = *(const float4*)(Ab + k0);
        float4 av1 = *(const float4*)(Ab + k0 + 4);
        float4 bv0 = *(const float4*)(Bb + k0);
        float4 bv1 = *(const float4*)(Bb + k0 + 4);
        __syncthreads();
        As[lko + 0][lrow] = f2tf32(av0.x); As[lko + 1][lrow] = f2tf32(av0.y);
        As[lko + 2][lrow] = f2tf32(av0.z); As[lko + 3][lrow] = f2tf32(av0.w);
        As[lko + 4][lrow] = f2tf32(av1.x); As[lko + 5][lrow] = f2tf32(av1.y);
        As[lko + 6][lrow] = f2tf32(av1.z); As[lko + 7][lrow] = f2tf32(av1.w);
        Bs[lko + 0][lrow] = f2tf32(bv0.x); Bs[lko + 1][lrow] = f2tf32(bv0.y);
        Bs[lko + 2][lrow] = f2tf32(bv0.z); Bs[lko + 3][lrow] = f2tf32(bv0.w);
        Bs[lko + 4][lrow] = f2tf32(bv1.x); Bs[lko + 5][lrow] = f2tf32(bv1.y);
        Bs[lko + 6][lrow] = f2tf32(bv1.z); Bs[lko + 7][lrow] = f2tf32(bv1.w);
        __syncthreads();

#pragma unroll
        for (int ks = 0; ks < 16; ks += 8) {
            uint32_t bf[4][2];
#pragma unroll
            for (int nt = 0; nt < 4; nt++) {
                bf[nt][0] = Bs[ks + tig][wn + nt * 8 + gid];
                bf[nt][1] = Bs[ks + tig + 4][wn + nt * 8 + gid];
            }
#pragma unroll
            for (int mt = 0; mt < 4; mt++) {
                uint32_t a0 = As[ks + tig][wm + mt * 16 + gid];
                uint32_t a1 = As[ks + tig][wm + mt * 16 + gid + 8];
                uint32_t a2 = As[ks + tig + 4][wm + mt * 16 + gid];
                uint32_t a3 = As[ks + tig + 4][wm + mt * 16 + gid + 8];
#pragma unroll
                for (int nt = 0; nt < 4; nt++)
                    mma_tf32(acc[mt][nt], a0, a1, a2, a3, bf[nt][0], bf[nt][1]);
            }
        }
    }

    // ---- epilogue ----
    const int rbase = blockIdx.y * 128 + wm + gid;
    const int cbase = blockIdx.x * 128 + wn + 2 * tig;

    if (MODE == 0) {
        float* Cb = C + blockIdx.z * sC;
#pragma unroll
        for (int mt = 0; mt < 4; mt++) {
#pragma unroll
            for (int nt = 0; nt < 4; nt++) {
                int r0 = rbase + mt * 16;
                int cc = cbase + nt * 8;
                *(float2*)(&Cb[(size_t)r0 * N + cc]) =
                    make_float2(acc[mt][nt][0] * alpha, acc[mt][nt][1] * alpha);
                *(float2*)(&Cb[(size_t)(r0 + 8) * N + cc]) =
                    make_float2(acc[mt][nt][2] * alpha, acc[mt][nt][3] * alpha);
            }
        }
    } else {
#pragma unroll
        for (int mt = 0; mt < 4; mt++) {
#pragma unroll
            for (int nt = 0; nt < 4; nt++) {
                int r0 = rbase + mt * 16;
                int cc = cbase + nt * 8;
                int h = cc >> 6, d = cc & 63;
                int b0 = r0 >> 11, t0 = r0 & 2047;
                int r1 = r0 + 8;
                int b1 = r1 >> 11, t1 = r1 & 2047;
                *(float2*)(C + ((size_t)(b0 * Hv + h) * Tv + t0) * Dv + d) =
                    make_float2(acc[mt][nt][0], acc[mt][nt][1]);
                *(float2*)(C + ((size_t)(b1 * Hv + h) * Tv + t1) * Dv + d) =
                    make_float2(acc[mt][nt][2], acc[mt][nt][3]);
            }
        }
    }
}

// ============================================================================
// Fused softmax stats + head-mean output (unchanged from R2).
// ============================================================================
__global__ void __launch_bounds__(256)
stats_mean(const float* __restrict__ S, float* __restrict__ Mv,
           float* __restrict__ Linv, float* __restrict__ meanout)
{
    const int bt   = blockIdx.x;
    const int b    = bt >> 11;
    const int t    = bt & 2047;
    const int tid  = threadIdx.x;
    const int lane = tid & 31;
    const int wid  = tid >> 5;

    __shared__ float red[8];

    float acc[8];
#pragma unroll
    for (int i = 0; i < 8; i++) acc[i] = 0.0f;

    for (int h = 0; h < Hv; h++) {
        const size_t base = ((size_t)(b * Hv + h) * Tv + t) * Tv;
        float v[8];
#pragma unroll
        for (int i = 0; i < 8; i++) v[i] = S[base + tid + i * 256];

        float m = v[0];
#pragma unroll
        for (int i = 1; i < 8; i++) m = fmaxf(m, v[i]);
#pragma unroll
        for (int o = 16; o > 0; o >>= 1)
            m = fmaxf(m, __shfl_xor_sync(0xffffffffu, m, o));
        if (lane == 0) red[wid] = m;
        __syncthreads();
        m = red[0];
#pragma unroll
        for (int i = 1; i < 8; i++) m = fmaxf(m, red[i]);

        float e[8];
        float l = 0.0f;
#pragma unroll
        for (int i = 0; i < 8; i++) { e[i] = __expf(v[i] - m); l += e[i]; }
#pragma unroll
        for (int o = 16; o > 0; o >>= 1)
            l += __shfl_xor_sync(0xffffffffu, l, o);
        __syncthreads();
        if (lane == 0) red[wid] = l;
        __syncthreads();
        l = red[0];
#pragma unroll
        for (int i = 1; i < 8; i++) l += red[i];
        const float linv = 1.0f / l;

        if (tid == 0) {
            Mv[(b * Hv + h) * Tv + t]   = m;
            Linv[(b * Hv + h) * Tv + t] = linv;
        }
#pragma unroll
        for (int i = 0; i < 8; i++) acc[i] += e[i] * linv;
        __syncthreads();
    }

    const size_t mb = (size_t)bt * Tv;
#pragma unroll
    for (int i = 0; i < 8; i++)
        meanout[mb + tid + i * 256] = acc[i] * (1.0f / Hv);
}

// ============================================================================
// P @ V tensor-core GEMM with softmax fused into the A-tile load:
//   p[t,s] = __expf(S[t,s] - m[t]) * linv[t]
// per (b,h): AV[t,d] = sum_s p[t,s] * V[s,d]
// 128x64 tile, 256 threads (8 warps, 4Mx2N), warp tile 32x32, BK=16.
// Fused store into g_AV layout [b, t, h*D + d].
// ============================================================================
__global__ void __launch_bounds__(256)
pv_gemm_tc(const float* __restrict__ S, const float* __restrict__ V,
           const float* __restrict__ Mv, const float* __restrict__ Linv,
           float* __restrict__ AV)
{
    __shared__ uint32_t As[16][133];  // [k][m]  (k = s)
    __shared__ uint32_t Bs[16][69];   // [k][n]  (n = d)

    const int tid  = threadIdx.x;
    const int lane = tid & 31;
    const int w    = tid >> 5;
    const int gid  = lane >> 2;
    const int tig  = lane & 3;
    const int wm   = (w & 3) * 32;  // 4 warps in M
    const int wn   = (w >> 2) * 32; // 2 warps in N

    const int lrow = tid >> 1;
    const int lko  = (tid & 1) * 8;
    const int bh   = blockIdx.z;

    const int arow   = blockIdx.y * 128 + lrow;
    const float mrow = Mv[bh * Tv + arow];
    const float lnv  = Linv[bh * Tv + arow];

    const float* Pb = S + (size_t)bh * Tv * Tv + (size_t)arow * Tv + lko;
    const float* Vb = V + (size_t)bh * Tv * Dv;

    const int bk = tid >> 4;          // 0..15
    const int bn = (tid & 15) * 4;    // 0..60

    float acc[2][4][4];
#pragma unroll
    for (int mt = 0; mt < 2; mt++)
#pragma unroll
        for (int nt = 0; nt < 4; nt++)
#pragma unroll
            for (int i = 0; i < 4; i++) acc[mt][nt][i] = 0.0f;

    for (int k0 = 0; k0 < Tv; k0 += 16) {
        float4 av0 = *(const float4*)(Pb + k0);
        float4 av1 = *(const float4*)(Pb + k0 + 4);
        float4 bv  = *(const float4*)(Vb + (size_t)(k0 + bk) * Dv + bn);
        __syncthreads();
        As[lko + 0][lrow] = f2tf32(__expf(av0.x - mrow) * lnv);
        As[lko + 1][lrow] = f2tf32(__expf(av0.y - mrow) * lnv);
        As[lko + 2][lrow] = f2tf32(__expf(av0.z - mrow) * lnv);
        As[lko + 3][lrow] = f2tf32(__expf(av0.w - mrow) * lnv);
        As[lko + 4][lrow] = f2tf32(__expf(av1.x - mrow) * lnv);
        As[lko + 5][lrow] = f2tf32(__expf(av1.y - mrow) * lnv);
        As[lko + 6][lrow] = f2tf32(__expf(av1.z - mrow) * lnv);
        As[lko + 7][lrow] = f2tf32(__expf(av1.w - mrow) * lnv);
        Bs[bk][bn + 0] = f2tf32(bv.x);
        Bs[bk][bn + 1] = f2tf32(bv.y);
        Bs[bk][bn + 2] = f2tf32(bv.z);
        Bs[bk][bn + 3] = f2tf32(bv.w);
        __syncthreads();

#pragma unroll
        for (int ks = 0; ks < 16; ks += 8) {
            uint32_t bf[4][2];
#pragma unroll
            for (int nt = 0; nt < 4; nt++) {
                bf[nt][0] = Bs[ks + tig][wn + nt * 8 + gid];
                bf[nt][1] = Bs[ks + tig + 4][wn + nt * 8 + gid];
            }
#pragma unroll
            for (int mt = 0; mt < 2; mt++) {
                uint32_t a0 = As[ks + tig][wm + mt * 16 + gid];
                uint32_t a1 = As[ks + tig][wm + mt * 16 + gid + 8];
                uint32_t a2 = As[ks + tig + 4][wm + mt * 16 + gid];
                uint32_t a3 = As[ks + tig + 4][wm + mt * 16 + gid + 8];
#pragma unroll
                for (int nt = 0; nt < 4; nt++)
                    mma_tf32(acc[mt][nt], a0, a1, a2, a3, bf[nt][0], bf[nt][1]);
            }
        }
    }

    const int b = bh / Hv, h = bh % Hv;
    const int rbase = blockIdx.y * 128 + wm + gid;
#pragma unroll
    for (int mt = 0; mt < 2; mt++) {
#pragma unroll
        for (int nt = 0; nt < 4; nt++) {
            int t0 = rbase + mt * 16;
            int d  = wn + nt * 8 + 2 * tig;
            *(float2*)(AV + ((size_t)b * Tv + t0) * HDv + h * Dv + d) =
                make_float2(acc[mt][nt][0], acc[mt][nt][1]);
            *(float2*)(AV + ((size_t)b * Tv + t0 + 8) * HDv + h * Dv + d) =
                make_float2(acc[mt][nt][2], acc[mt][nt][3]);
        }
    }
}

// ============================================================================
// Launch
// ============================================================================
extern "C" void kernel_launch(void* const* d_in, const int* in_sizes, int n_in,
                              void* d_out, int out_size)
{
    const float* q  = (const float*)d_in[0];
    const float* k  = (const float*)d_in[1];
    const float* v  = (const float*)d_in[2];
    const float* Wq = (const float*)d_in[3];
    const float* Wk = (const float*)d_in[4];
    const float* Wv = (const float*)d_in[5];
    const float* Wo = (const float*)d_in[6];

    float* xout    = (float*)d_out;                                        // [B,T,E]
    float* meanout = (float*)d_out + ((size_t)out_size - (size_t)Bv * Tv * Tv); // [B,T,T]

    float *pQ, *pK, *pV, *pS, *pM, *pL, *pAV;
    cudaGetSymbolAddress((void**)&pQ,  g_Q);
    cudaGetSymbolAddress((void**)&pK,  g_K);
    cudaGetSymbolAddress((void**)&pV,  g_V);
    cudaGetSymbolAddress((void**)&pS,  g_S);
    cudaGetSymbolAddress((void**)&pM,  g_M);
    cudaGetSymbolAddress((void**)&pL,  g_Linv);
    cudaGetSymbolAddress((void**)&pAV, g_AV);

    dim3 thr(256);

    // 1) Projections: [BT,E] @ W^T -> [b,h,t,d]
    dim3 gProj(HDv / 128, BTv / 128, 1);
    gemm_nt_tc<1><<<gProj, thr>>>(q, Wq, pQ, BTv, HDv, Ev, 0, 0, 0, 1.0f);
    gemm_nt_tc<1><<<gProj, thr>>>(k, Wk, pK, BTv, HDv, Ev, 0, 0, 0, 1.0f);
    gemm_nt_tc<1><<<gProj, thr>>>(v, Wv, pV, BTv, HDv, Ev, 0, 0, 0, 1.0f);

    // 2) Scores: per (b,h), S = Q K^T / sqrt(D)
    dim3 gScore(Tv / 128, Tv / 128, BHv);
    gemm_nt_tc<0><<<gScore, thr>>>(pQ, pK, pS, Tv, Tv, Dv,
                                   (size_t)Tv * Dv, (size_t)Tv * Dv,
                                   (size_t)Tv * Tv, 0.125f);

    // 3) Fused softmax stats + head-mean (reads S once, writes mean to d_out)
    stats_mean<<<BTv, 256>>>(pS, pM, pL, meanout);

    // 4) attn @ V with fused normalization -> g_AV [b,t,h*D]
    pv_gemm_tc<<<dim3(1, Tv / 128, BHv), 256>>>(pS, pV, pM, pL, pAV);

    // 5) Output projection: [BT,HD] @ Wo^T -> x
    dim3 gOut(Ev / 128, BTv / 128, 1);
    gemm_nt_tc<0><<<gOut, thr>>>(pAV, Wo, xout, BTv, Ev, HDv, 0, 0, 0, 1.0f);
}

// round 4
// speedup vs baseline: 1.8165x; 1.3812x over previous
#include <cuda_runtime.h>
#include <math.h>
#include <stdint.h>

// Problem constants
#define Bv  4
#define Tv  2048
#define Ev  1024
#define Hv  16
#define Dv  64
#define HDv 1024      // H*D
#define BTv 8192      // B*T
#define BHv 64        // B*H

// -------- scratch (device globals; no runtime allocation) --------
static __device__ float g_Q[(size_t)BHv * Tv * Dv];          // [b,h,t,d]
static __device__ float g_K[(size_t)BHv * Tv * Dv];
static __device__ float g_V[(size_t)BHv * Tv * Dv];
static __device__ float g_S[(size_t)BHv * Tv * Tv];          // raw scores (1 GiB)
static __device__ float g_M[BHv * Tv];                       // row max
static __device__ float g_Linv[BHv * Tv];                    // 1 / row sumexp
static __device__ float g_AV[(size_t)BTv * HDv];             // attn out, [b,t,h*D+d]

// ---------------- tf32 helpers ----------------
__device__ __forceinline__ uint32_t f2tf32(float f) {
    uint32_t u;
    asm("cvt.rna.tf32.f32 %0, %1;" : "=r"(u) : "f"(f));
    return u;
}

__device__ __forceinline__ void mma_tf32(float c[4],
        uint32_t a0, uint32_t a1, uint32_t a2, uint32_t a3,
        uint32_t b0, uint32_t b1)
{
    asm volatile(
        "mma.sync.aligned.m16n8k8.row.col.f32.tf32.tf32.f32 "
        "{%0,%1,%2,%3}, {%4,%5,%6,%7}, {%8,%9}, {%0,%1,%2,%3};"
        : "+f"(c[0]), "+f"(c[1]), "+f"(c[2]), "+f"(c[3])
        : "r"(a0), "r"(a1), "r"(a2), "r"(a3), "r"(b0), "r"(b1));
}

// ============================================================================
// Tensor-core NT GEMM v2: C[M,N] = alpha * A * B^T. A:[M,K] ld=K, B:[N,K] ld=K.
// 128x128 block tile, 128 threads (4 warps in 2Mx2N), warp tile 64x64,
// m16n8k8 tf32 mma, BK=16, register double-buffered global loads.
// Each thread owns one tile row for loading (row = tid, all 16 k).
// MODE 0: row-major C (ldc=N), batched via blockIdx.z strides, scaled by alpha
// MODE 1: projection store: row=(b,t), col=(h,d) -> C[((b*H+h)*T+t)*D+d]
// ============================================================================
template <int MODE>
__global__ void __launch_bounds__(128)
gemm_nt_tc(const float* __restrict__ A, const float* __restrict__ Bm,
           float* __restrict__ C, int M, int N, int K,
           size_t sA, size_t sB, size_t sC, float alpha)
{
    __shared__ uint32_t As[16][132];   // [k][m]
    __shared__ uint32_t Bs[16][132];   // [k][n]

    const int tid  = threadIdx.x;
    const int lane = tid & 31;
    const int w    = tid >> 5;
    const int gid  = lane >> 2;     // 0..7
    const int tig  = lane & 3;      // 0..3
    const int wm   = (w & 1) * 64;
    const int wn   = (w >> 1) * 64;

    const float* Ab = A + blockIdx.z * sA + (size_t)(blockIdx.y * 128 + tid) * K;
    const float* Bb = Bm + blockIdx.z * sB + (size_t)(blockIdx.x * 128 + tid) * K;

    // prefetch registers (one BK=16 strip of this thread's row)
    float4 pa0, pa1, pa2, pa3, pb0, pb1, pb2, pb3;
    pa0 = *(const float4*)(Ab + 0);  pa1 = *(const float4*)(Ab + 4);
    pa2 = *(const float4*)(Ab + 8);  pa3 = *(const float4*)(Ab + 12);
    pb0 = *(const float4*)(Bb + 0);  pb1 = *(const float4*)(Bb + 4);
    pb2 = *(const float4*)(Bb + 8);  pb3 = *(const float4*)(Bb + 12);

    float acc[4][8][4];
#pragma unroll
    for (int mt = 0; mt < 4; mt++)
#pragma unroll
        for (int nt = 0; nt < 8; nt++)
#pragma unroll
            for (int i = 0; i < 4; i++) acc[mt][nt][i] = 0.0f;

    for (int k0 = 0; k0 < K; k0 += 16) {
        __syncthreads();
        As[0][tid]  = f2tf32(pa0.x); As[1][tid]  = f2tf32(pa0.y);
        As[2][tid]  = f2tf32(pa0.z); As[3][tid]  = f2tf32(pa0.w);
        As[4][tid]  = f2tf32(pa1.x); As[5][tid]  = f2tf32(pa1.y);
        As[6][tid]  = f2tf32(pa1.z); As[7][tid]  = f2tf32(pa1.w);
        As[8][tid]  = f2tf32(pa2.x); As[9][tid]  = f2tf32(pa2.y);
        As[10][tid] = f2tf32(pa2.z); As[11][tid] = f2tf32(pa2.w);
        As[12][tid] = f2tf32(pa3.x); As[13][tid] = f2tf32(pa3.y);
        As[14][tid] = f2tf32(pa3.z); As[15][tid] = f2tf32(pa3.w);
        Bs[0][tid]  = f2tf32(pb0.x); Bs[1][tid]  = f2tf32(pb0.y);
        Bs[2][tid]  = f2tf32(pb0.z); Bs[3][tid]  = f2tf32(pb0.w);
        Bs[4][tid]  = f2tf32(pb1.x); Bs[5][tid]  = f2tf32(pb1.y);
        Bs[6][tid]  = f2tf32(pb1.z); Bs[7][tid]  = f2tf32(pb1.w);
        Bs[8][tid]  = f2tf32(pb2.x); Bs[9][tid]  = f2tf32(pb2.y);
        Bs[10][tid] = f2tf32(pb2.z); Bs[11][tid] = f2tf32(pb2.w);
        Bs[12][tid] = f2tf32(pb3.x); Bs[13][tid] = f2tf32(pb3.y);
        Bs[14][tid] = f2tf32(pb3.z); Bs[15][tid] = f2tf32(pb3.w);
        __syncthreads();

        // prefetch next k-strip while mmas run on shared
        const int kn = k0 + 16;
        if (kn < K) {
            pa0 = *(const float4*)(Ab + kn);      pa1 = *(const float4*)(Ab + kn + 4);
            pa2 = *(const float4*)(Ab + kn + 8);  pa3 = *(const float4*)(Ab + kn + 12);
            pb0 = *(const float4*)(Bb + kn);      pb1 = *(const float4*)(Bb + kn + 4);
            pb2 = *(const float4*)(Bb + kn + 8);  pb3 = *(const float4*)(Bb + kn + 12);
        }

#pragma unroll
        for (int ks = 0; ks < 16; ks += 8) {
            uint32_t bf[8][2];
#pragma unroll
            for (int nt = 0; nt < 8; nt++) {
                bf[nt][0] = Bs[ks + tig][wn + nt * 8 + gid];
                bf[nt][1] = Bs[ks + tig + 4][wn + nt * 8 + gid];
            }
#pragma unroll
            for (int mt = 0; mt < 4; mt++) {
                uint32_t a0 = As[ks + tig][wm + mt * 16 + gid];
                uint32_t a1 = As[ks + tig][wm + mt * 16 + gid + 8];
                uint32_t a2 = As[ks + tig + 4][wm + mt * 16 + gid];
                uint32_t a3 = As[ks + tig + 4][wm + mt * 16 + gid + 8];
#pragma unroll
                for (int nt = 0; nt < 8; nt++)
                    mma_tf32(acc[mt][nt], a0, a1, a2, a3, bf[nt][0], bf[nt][1]);
            }
        }
    }

    // ---- epilogue ----
    if (MODE == 0) {
        float* Cb = C + blockIdx.z * sC;
#pragma unroll
        for (int mt = 0; mt < 4; mt++) {
            const int r0 = blockIdx.y * 128 + wm + mt * 16 + gid;
#pragma unroll
            for (int nt = 0; nt < 8; nt++) {
                const int cc = blockIdx.x * 128 + wn + nt * 8 + 2 * tig;
                *(float2*)(&Cb[(size_t)r0 * N + cc]) =
                    make_float2(acc[mt][nt][0] * alpha, acc[mt][nt][1] * alpha);
                *(float2*)(&Cb[(size_t)(r0 + 8) * N + cc]) =
                    make_float2(acc[mt][nt][2] * alpha, acc[mt][nt][3] * alpha);
            }
        }
    } else {
#pragma unroll
        for (int mt = 0; mt < 4; mt++) {
            const int r0 = blockIdx.y * 128 + wm + mt * 16 + gid;
            const int b0 = r0 >> 11, t0 = r0 & 2047;
            const int r1 = r0 + 8;
            const int b1 = r1 >> 11, t1 = r1 & 2047;
#pragma unroll
            for (int nt = 0; nt < 8; nt++) {
                const int cc = blockIdx.x * 128 + wn + nt * 8 + 2 * tig;
                const int h = cc >> 6, d = cc & 63;
                *(float2*)(C + ((size_t)(b0 * Hv + h) * Tv + t0) * Dv + d) =
                    make_float2(acc[mt][nt][0], acc[mt][nt][1]);
                *(float2*)(C + ((size_t)(b1 * Hv + h) * Tv + t1) * Dv + d) =
                    make_float2(acc[mt][nt][2], acc[mt][nt][3]);
            }
        }
    }
}

// ============================================================================
// Fused softmax stats + head-mean output (unchanged).
// ============================================================================
__global__ void __launch_bounds__(256)
stats_mean(const float* __restrict__ S, float* __restrict__ Mv,
           float* __restrict__ Linv, float* __restrict__ meanout)
{
    const int bt   = blockIdx.x;
    const int b    = bt >> 11;
    const int t    = bt & 2047;
    const int tid  = threadIdx.x;
    const int lane = tid & 31;
    const int wid  = tid >> 5;

    __shared__ float red[8];

    float acc[8];
#pragma unroll
    for (int i = 0; i < 8; i++) acc[i] = 0.0f;

    for (int h = 0; h < Hv; h++) {
        const size_t base = ((size_t)(b * Hv + h) * Tv + t) * Tv;
        float v[8];
#pragma unroll
        for (int i = 0; i < 8; i++) v[i] = S[base + tid + i * 256];

        float m = v[0];
#pragma unroll
        for (int i = 1; i < 8; i++) m = fmaxf(m, v[i]);
#pragma unroll
        for (int o = 16; o > 0; o >>= 1)
            m = fmaxf(m, __shfl_xor_sync(0xffffffffu, m, o));
        if (lane == 0) red[wid] = m;
        __syncthreads();
        m = red[0];
#pragma unroll
        for (int i = 1; i < 8; i++) m = fmaxf(m, red[i]);

        float e[8];
        float l = 0.0f;
#pragma unroll
        for (int i = 0; i < 8; i++) { e[i] = __expf(v[i] - m); l += e[i]; }
#pragma unroll
        for (int o = 16; o > 0; o >>= 1)
            l += __shfl_xor_sync(0xffffffffu, l, o);
        __syncthreads();
        if (lane == 0) red[wid] = l;
        __syncthreads();
        l = red[0];
#pragma unroll
        for (int i = 1; i < 8; i++) l += red[i];
        const float linv = 1.0f / l;

        if (tid == 0) {
            Mv[(b * Hv + h) * Tv + t]   = m;
            Linv[(b * Hv + h) * Tv + t] = linv;
        }
#pragma unroll
        for (int i = 0; i < 8; i++) acc[i] += e[i] * linv;
        __syncthreads();
    }

    const size_t mb = (size_t)bt * Tv;
#pragma unroll
    for (int i = 0; i < 8; i++)
        meanout[mb + tid + i * 256] = acc[i] * (1.0f / Hv);
}

// ============================================================================
// P @ V tensor-core GEMM with fused softmax normalization (unchanged).
// ============================================================================
__global__ void __launch_bounds__(256)
pv_gemm_tc(const float* __restrict__ S, const float* __restrict__ V,
           const float* __restrict__ Mv, const float* __restrict__ Linv,
           float* __restrict__ AV)
{
    __shared__ uint32_t As[16][133];  // [k][m]  (k = s)
    __shared__ uint32_t Bs[16][69];   // [k][n]  (n = d)

    const int tid  = threadIdx.x;
    const int lane = tid & 31;
    const int w    = tid >> 5;
    const int gid  = lane >> 2;
    const int tig  = lane & 3;
    const int wm   = (w & 3) * 32;
    const int wn   = (w >> 2) * 32;

    const int lrow = tid >> 1;
    const int lko  = (tid & 1) * 8;
    const int bh   = blockIdx.z;

    const int arow   = blockIdx.y * 128 + lrow;
    const float mrow = Mv[bh * Tv + arow];
    const float lnv  = Linv[bh * Tv + arow];

    const float* Pb = S + (size_t)bh * Tv * Tv + (size_t)arow * Tv + lko;
    const float* Vb = V + (size_t)bh * Tv * Dv;

    const int bk = tid >> 4;
    const int bn = (tid & 15) * 4;

    float acc[2][4][4];
#pragma unroll
    for (int mt = 0; mt < 2; mt++)
#pragma unroll
        for (int nt = 0; nt < 4; nt++)
#pragma unroll
            for (int i = 0; i < 4; i++) acc[mt][nt][i] = 0.0f;

    for (int k0 = 0; k0 < Tv; k0 += 16) {
        float4 av0 = *(const float4*)(Pb + k0);
        float4 av1 = *(const float4*)(Pb + k0 + 4);
        float4 bv  = *(const float4*)(Vb + (size_t)(k0 + bk) * Dv + bn);
        __syncthreads();
        As[lko + 0][lrow] = f2tf32(__expf(av0.x - mrow) * lnv);
        As[lko + 1][lrow] = f2tf32(__expf(av0.y - mrow) * lnv);
        As[lko + 2][lrow] = f2tf32(__expf(av0.z - mrow) * lnv);
        As[lko + 3][lrow] = f2tf32(__expf(av0.w - mrow) * lnv);
        As[lko + 4][lrow] = f2tf32(__expf(av1.x - mrow) * lnv);
        As[lko + 5][lrow] = f2tf32(__expf(av1.y - mrow) * lnv);
        As[lko + 6][lrow] = f2tf32(__expf(av1.z - mrow) * lnv);
        As[lko + 7][lrow] = f2tf32(__expf(av1.w - mrow) * lnv);
        Bs[bk][bn + 0] = f2tf32(bv.x);
        Bs[bk][bn + 1] = f2tf32(bv.y);
        Bs[bk][bn + 2] = f2tf32(bv.z);
        Bs[bk][bn + 3] = f2tf32(bv.w);
        __syncthreads();

#pragma unroll
        for (int ks = 0; ks < 16; ks += 8) {
            uint32_t bf[4][2];
#pragma unroll
            for (int nt = 0; nt < 4; nt++) {
                bf[nt][0] = Bs[ks + tig][wn + nt * 8 + gid];
                bf[nt][1] = Bs[ks + tig + 4][wn + nt * 8 + gid];
            }
#pragma unroll
            for (int mt = 0; mt < 2; mt++) {
                uint32_t a0 = As[ks + tig][wm + mt * 16 + gid];
                uint32_t a1 = As[ks + tig][wm + mt * 16 + gid + 8];
                uint32_t a2 = As[ks + tig + 4][wm + mt * 16 + gid];
                uint32_t a3 = As[ks + tig + 4][wm + mt * 16 + gid + 8];
#pragma unroll
                for (int nt = 0; nt < 4; nt++)
                    mma_tf32(acc[mt][nt], a0, a1, a2, a3, bf[nt][0], bf[nt][1]);
            }
        }
    }

    const int b = bh / Hv, h = bh % Hv;
    const int rbase = blockIdx.y * 128 + wm + gid;
#pragma unroll
    for (int mt = 0; mt < 2; mt++) {
#pragma unroll
        for (int nt = 0; nt < 4; nt++) {
            int t0 = rbase + mt * 16;
            int d  = wn + nt * 8 + 2 * tig;
            *(float2*)(AV + ((size_t)b * Tv + t0) * HDv + h * Dv + d) =
                make_float2(acc[mt][nt][0], acc[mt][nt][1]);
            *(float2*)(AV + ((size_t)b * Tv + t0 + 8) * HDv + h * Dv + d) =
                make_float2(acc[mt][nt][2], acc[mt][nt][3]);
        }
    }
}

// ============================================================================
// Launch
// ============================================================================
extern "C" void kernel_launch(void* const* d_in, const int* in_sizes, int n_in,
                              void* d_out, int out_size)
{
    const float* q  = (const float*)d_in[0];
    const float* k  = (const float*)d_in[1];
    const float* v  = (const float*)d_in[2];
    const float* Wq = (const float*)d_in[3];
    const float* Wk = (const float*)d_in[4];
    const float* Wv = (const float*)d_in[5];
    const float* Wo = (const float*)d_in[6];

    float* xout    = (float*)d_out;                                        // [B,T,E]
    float* meanout = (float*)d_out + ((size_t)out_size - (size_t)Bv * Tv * Tv); // [B,T,T]

    float *pQ, *pK, *pV, *pS, *pM, *pL, *pAV;
    cudaGetSymbolAddress((void**)&pQ,  g_Q);
    cudaGetSymbolAddress((void**)&pK,  g_K);
    cudaGetSymbolAddress((void**)&pV,  g_V);
    cudaGetSymbolAddress((void**)&pS,  g_S);
    cudaGetSymbolAddress((void**)&pM,  g_M);
    cudaGetSymbolAddress((void**)&pL,  g_Linv);
    cudaGetSymbolAddress((void**)&pAV, g_AV);

    dim3 thr(128);

    // 1) Projections: [BT,E] @ W^T -> [b,h,t,d]
    dim3 gProj(HDv / 128, BTv / 128, 1);
    gemm_nt_tc<1><<<gProj, thr>>>(q, Wq, pQ, BTv, HDv, Ev, 0, 0, 0, 1.0f);
    gemm_nt_tc<1><<<gProj, thr>>>(k, Wk, pK, BTv, HDv, Ev, 0, 0, 0, 1.0f);
    gemm_nt_tc<1><<<gProj, thr>>>(v, Wv, pV, BTv, HDv, Ev, 0, 0, 0, 1.0f);

    // 2) Scores: per (b,h), S = Q K^T / sqrt(D)
    dim3 gScore(Tv / 128, Tv / 128, BHv);
    gemm_nt_tc<0><<<gScore, thr>>>(pQ, pK, pS, Tv, Tv, Dv,
                                   (size_t)Tv * Dv, (size_t)Tv * Dv,
                                   (size_t)Tv * Tv, 0.125f);

    // 3) Fused softmax stats + head-mean (reads S once, writes mean to d_out)
    stats_mean<<<BTv, 256>>>(pS, pM, pL, meanout);

    // 4) attn @ V with fused normalization -> g_AV [b,t,h*D]
    pv_gemm_tc<<<dim3(1, Tv / 128, BHv), 256>>>(pS, pV, pM, pL, pAV);

    // 5) Output projection: [BT,HD] @ Wo^T -> x
    dim3 gOut(Ev / 128, BTv / 128, 1);
    gemm_nt_tc<0><<<gOut, thr>>>(pAV, Wo, xout, BTv, Ev, HDv, 0, 0, 0, 1.0f);
}

// round 6
// speedup vs baseline: 2.3968x; 1.3194x over previous
#include <cuda_runtime.h>
#include <cuda_fp16.h>
#include <math.h>
#include <stdint.h>

// Problem constants
#define Bv  4
#define Tv  2048
#define Ev  1024
#define Hv  16
#define Dv  64
#define HDv 1024      // H*D
#define BTv 8192      // B*T
#define BHv 64        // B*H

// -------- scratch (device globals; no runtime allocation) --------
static __device__ float g_Q[(size_t)BHv * Tv * Dv];          // [b,h,t,d]
static __device__ float g_K[(size_t)BHv * Tv * Dv];
static __device__ float g_V[(size_t)BHv * Tv * Dv];
static __device__ float g_S[(size_t)BHv * Tv * Tv];          // raw scores (1 GiB)
static __device__ float g_M[BHv * Tv];                       // row max
static __device__ float g_Linv[BHv * Tv];                    // 1 / row sumexp
static __device__ float g_AV[(size_t)BTv * HDv];             // attn out, [b,t,h*D+d]

// ---------------- fp16 helpers ----------------
__device__ __forceinline__ uint32_t f2h2(float x, float y) {
    __half2 h = __floats2half2_rn(x, y);
    return *reinterpret_cast<uint32_t*>(&h);
}

// m16n8k16 fp16 mma, fp32 accumulate
__device__ __forceinline__ void mma_f16(float c[4],
        uint32_t a0, uint32_t a1, uint32_t a2, uint32_t a3,
        uint32_t b0, uint32_t b1)
{
    asm volatile(
        "mma.sync.aligned.m16n8k16.row.col.f32.f16.f16.f32 "
        "{%0,%1,%2,%3}, {%4,%5,%6,%7}, {%8,%9}, {%0,%1,%2,%3};"
        : "+f"(c[0]), "+f"(c[1]), "+f"(c[2]), "+f"(c[3])
        : "r"(a0), "r"(a1), "r"(a2), "r"(a3), "r"(b0), "r"(b1));
}

// ============================================================================
// fp16 tensor-core NT GEMM: C[M,N] = alpha * A * B^T. A:[M,K] ld=K, B:[N,K] ld=K.
// 128x128 block tile, 128 threads (4 warps in 2Mx2N), warp tile 64x64,
// m16n8k16 mma, BK=32 (2 k16-steps per shared tile), register-prefetched loads.
// Shared layout: [k-pair][row], each element = half2 packing (k, k+1).
// MODE 0: row-major C (ldc=N), batched via blockIdx.z strides, scaled by alpha
// MODE 1: projection store: row=(b,t), col=(h,d) -> C[((b*H+h)*T+t)*D+d]
// ============================================================================
template <int MODE>
__global__ void __launch_bounds__(128)
gemm_nt_h(const float* __restrict__ A, const float* __restrict__ Bm,
          float* __restrict__ C, int M, int N, int K,
          size_t sA, size_t sB, size_t sC, float alpha)
{
    __shared__ uint32_t As[16][132];   // [k-pair][m], BK=32
    __shared__ uint32_t Bs[16][132];   // [k-pair][n]

    const int tid  = threadIdx.x;
    const int lane = tid & 31;
    const int w    = tid >> 5;
    const int gid  = lane >> 2;     // 0..7
    const int tig  = lane & 3;      // 0..3
    const int wm   = (w & 1) * 64;
    const int wn   = (w >> 1) * 64;

    const float* Ab = A + blockIdx.z * sA + (size_t)(blockIdx.y * 128 + tid) * K;
    const float* Bb = Bm + blockIdx.z * sB + (size_t)(blockIdx.x * 128 + tid) * K;

    // prefetch registers: one BK=32 strip of this thread's row (8 float4 each)
    float4 pa[8], pb[8];
#pragma unroll
    for (int i = 0; i < 8; i++) {
        pa[i] = *(const float4*)(Ab + i * 4);
        pb[i] = *(const float4*)(Bb + i * 4);
    }

    float acc[4][8][4];
#pragma unroll
    for (int mt = 0; mt < 4; mt++)
#pragma unroll
        for (int nt = 0; nt < 8; nt++)
#pragma unroll
            for (int i = 0; i < 4; i++) acc[mt][nt][i] = 0.0f;

    for (int k0 = 0; k0 < K; k0 += 32) {
        __syncthreads();
#pragma unroll
        for (int i = 0; i < 8; i++) {
            As[2 * i][tid]     = f2h2(pa[i].x, pa[i].y);
            As[2 * i + 1][tid] = f2h2(pa[i].z, pa[i].w);
            Bs[2 * i][tid]     = f2h2(pb[i].x, pb[i].y);
            Bs[2 * i + 1][tid] = f2h2(pb[i].z, pb[i].w);
        }
        __syncthreads();

        // prefetch next BK strip while mmas run on shared
        const int kn = k0 + 32;
        if (kn < K) {
#pragma unroll
            for (int i = 0; i < 8; i++) {
                pa[i] = *(const float4*)(Ab + kn + i * 4);
                pb[i] = *(const float4*)(Bb + kn + i * 4);
            }
        }

#pragma unroll
        for (int ks = 0; ks < 16; ks += 8) {   // two k16 steps (8 pairs each)
            uint32_t bf[8][2];
#pragma unroll
            for (int nt = 0; nt < 8; nt++) {
                bf[nt][0] = Bs[ks + tig][wn + nt * 8 + gid];
                bf[nt][1] = Bs[ks + tig + 4][wn + nt * 8 + gid];
            }
#pragma unroll
            for (int mt = 0; mt < 4; mt++) {
                uint32_t a0 = As[ks + tig][wm + mt * 16 + gid];
                uint32_t a1 = As[ks + tig][wm + mt * 16 + gid + 8];
                uint32_t a2 = As[ks + tig + 4][wm + mt * 16 + gid];
                uint32_t a3 = As[ks + tig + 4][wm + mt * 16 + gid + 8];
#pragma unroll
                for (int nt = 0; nt < 8; nt++)
                    mma_f16(acc[mt][nt], a0, a1, a2, a3, bf[nt][0], bf[nt][1]);
            }
        }
    }

    // ---- epilogue ----
    if (MODE == 0) {
        float* Cb = C + blockIdx.z * sC;
#pragma unroll
        for (int mt = 0; mt < 4; mt++) {
            const int r0 = blockIdx.y * 128 + wm + mt * 16 + gid;
#pragma unroll
            for (int nt = 0; nt < 8; nt++) {
                const int cc = blockIdx.x * 128 + wn + nt * 8 + 2 * tig;
                *(float2*)(&Cb[(size_t)r0 * N + cc]) =
                    make_float2(acc[mt][nt][0] * alpha, acc[mt][nt][1] * alpha);
                *(float2*)(&Cb[(size_t)(r0 + 8) * N + cc]) =
                    make_float2(acc[mt][nt][2] * alpha, acc[mt][nt][3] * alpha);
            }
        }
    } else {
#pragma unroll
        for (int mt = 0; mt < 4; mt++) {
            const int r0 = blockIdx.y * 128 + wm + mt * 16 + gid;
            const int b0 = r0 >> 11, t0 = r0 & 2047;
            const int r1 = r0 + 8;
            const int b1 = r1 >> 11, t1 = r1 & 2047;
#pragma unroll
            for (int nt = 0; nt < 8; nt++) {
                const int cc = blockIdx.x * 128 + wn + nt * 8 + 2 * tig;
                const int h = cc >> 6, d = cc & 63;
                *(float2*)(C + ((size_t)(b0 * Hv + h) * Tv + t0) * Dv + d) =
                    make_float2(acc[mt][nt][0], acc[mt][nt][1]);
                *(float2*)(C + ((size_t)(b1 * Hv + h) * Tv + t1) * Dv + d) =
                    make_float2(acc[mt][nt][2], acc[mt][nt][3]);
            }
        }
    }
}

// ============================================================================
// Fused softmax stats + head-mean output (unchanged).
// ============================================================================
__global__ void __launch_bounds__(256)
stats_mean(const float* __restrict__ S, float* __restrict__ Mv,
           float* __restrict__ Linv, float* __restrict__ meanout)
{
    const int bt   = blockIdx.x;
    const int b    = bt >> 11;
    const int t    = bt & 2047;
    const int tid  = threadIdx.x;
    const int lane = tid & 31;
    const int wid  = tid >> 5;

    __shared__ float red[8];

    float acc[8];
#pragma unroll
    for (int i = 0; i < 8; i++) acc[i] = 0.0f;

    for (int h = 0; h < Hv; h++) {
        const size_t base = ((size_t)(b * Hv + h) * Tv + t) * Tv;
        float v[8];
#pragma unroll
        for (int i = 0; i < 8; i++) v[i] = S[base + tid + i * 256];

        float m = v[0];
#pragma unroll
        for (int i = 1; i < 8; i++) m = fmaxf(m, v[i]);
#pragma unroll
        for (int o = 16; o > 0; o >>= 1)
            m = fmaxf(m, __shfl_xor_sync(0xffffffffu, m, o));
        if (lane == 0) red[wid] = m;
        __syncthreads();
        m = red[0];
#pragma unroll
        for (int i = 1; i < 8; i++) m = fmaxf(m, red[i]);

        float e[8];
        float l = 0.0f;
#pragma unroll
        for (int i = 0; i < 8; i++) { e[i] = __expf(v[i] - m); l += e[i]; }
#pragma unroll
        for (int o = 16; o > 0; o >>= 1)
            l += __shfl_xor_sync(0xffffffffu, l, o);
        __syncthreads();
        if (lane == 0) red[wid] = l;
        __syncthreads();
        l = red[0];
#pragma unroll
        for (int i = 1; i < 8; i++) l += red[i];
        const float linv = 1.0f / l;

        if (tid == 0) {
            Mv[(b * Hv + h) * Tv + t]   = m;
            Linv[(b * Hv + h) * Tv + t] = linv;
        }
#pragma unroll
        for (int i = 0; i < 8; i++) acc[i] += e[i] * linv;
        __syncthreads();
    }

    const size_t mb = (size_t)bt * Tv;
#pragma unroll
    for (int i = 0; i < 8; i++)
        meanout[mb + tid + i * 256] = acc[i] * (1.0f / Hv);
}

// ============================================================================
// P @ V fp16 tensor-core GEMM with softmax fused into the A-tile load:
//   p[t,s] = __expf(S[t,s] - m[t]) * linv[t]  (converted to half2 pairs in s)
// per (b,h): AV[t,d] = sum_s p[t,s] * V[s,d]
// 128x64 tile, 256 threads (8 warps, 4Mx2N), warp tile 32x32, BK=32.
// Fused store into g_AV layout [b, t, h*D + d].
// ============================================================================
__global__ void __launch_bounds__(256)
pv_gemm_h(const float* __restrict__ S, const float* __restrict__ V,
          const float* __restrict__ Mv, const float* __restrict__ Linv,
          float* __restrict__ AV)
{
    __shared__ uint32_t As[16][132];  // [s-pair][t], BK=32
    __shared__ uint32_t Bs[16][68];   // [s-pair][d]

    const int tid  = threadIdx.x;
    const int lane = tid & 31;
    const int w    = tid >> 5;
    const int gid  = lane >> 2;
    const int tig  = lane & 3;
    const int wm   = (w & 3) * 32;
    const int wn   = (w >> 2) * 32;

    const int lrow = tid >> 1;          // 0..127: P row
    const int lko  = (tid & 1) * 16;    // 0 or 16: k (s) offset, 16 floats
    const int bh   = blockIdx.z;

    const int arow   = blockIdx.y * 128 + lrow;
    const float mrow = Mv[bh * Tv + arow];
    const float lnv  = Linv[bh * Tv + arow];

    const float* Pb = S + (size_t)bh * Tv * Tv + (size_t)arow * Tv + lko;
    const float* Vb = V + (size_t)bh * Tv * Dv;

    // V loader: thread handles k-pair k2 = tid>>4 (0..15), cols (tid&15)*4
    const int vk2 = tid >> 4;
    const int vn  = (tid & 15) * 4;

    float acc[2][4][4];
#pragma unroll
    for (int mt = 0; mt < 2; mt++)
#pragma unroll
        for (int nt = 0; nt < 4; nt++)
#pragma unroll
            for (int i = 0; i < 4; i++) acc[mt][nt][i] = 0.0f;

    for (int k0 = 0; k0 < Tv; k0 += 32) {
        float4 av[4];
#pragma unroll
        for (int i = 0; i < 4; i++) av[i] = *(const float4*)(Pb + k0 + i * 4);
        float4 bv0 = *(const float4*)(Vb + (size_t)(k0 + 2 * vk2) * Dv + vn);
        float4 bv1 = *(const float4*)(Vb + (size_t)(k0 + 2 * vk2 + 1) * Dv + vn);
        __syncthreads();
#pragma unroll
        for (int i = 0; i < 4; i++) {
            float e0 = __expf(av[i].x - mrow) * lnv;
            float e1 = __expf(av[i].y - mrow) * lnv;
            float e2 = __expf(av[i].z - mrow) * lnv;
            float e3 = __expf(av[i].w - mrow) * lnv;
            As[(lko >> 1) + 2 * i][lrow]     = f2h2(e0, e1);
            As[(lko >> 1) + 2 * i + 1][lrow] = f2h2(e2, e3);
        }
        Bs[vk2][vn + 0] = f2h2(bv0.x, bv1.x);
        Bs[vk2][vn + 1] = f2h2(bv0.y, bv1.y);
        Bs[vk2][vn + 2] = f2h2(bv0.z, bv1.z);
        Bs[vk2][vn + 3] = f2h2(bv0.w, bv1.w);
        __syncthreads();

#pragma unroll
        for (int ks = 0; ks < 16; ks += 8) {
            uint32_t bf[4][2];
#pragma unroll
            for (int nt = 0; nt < 4; nt++) {
                bf[nt][0] = Bs[ks + tig][wn + nt * 8 + gid];
                bf[nt][1] = Bs[ks + tig + 4][wn + nt * 8 + gid];
            }
#pragma unroll
            for (int mt = 0; mt < 2; mt++) {
                uint32_t a0 = As[ks + tig][wm + mt * 16 + gid];
                uint32_t a1 = As[ks + tig][wm + mt * 16 + gid + 8];
                uint32_t a2 = As[ks + tig + 4][wm + mt * 16 + gid];
                uint32_t a3 = As[ks + tig + 4][wm + mt * 16 + gid + 8];
#pragma unroll
                for (int nt = 0; nt < 4; nt++)
                    mma_f16(acc[mt][nt], a0, a1, a2, a3, bf[nt][0], bf[nt][1]);
            }
        }
    }

    const int b = bh / Hv, h = bh % Hv;
    const int rbase = blockIdx.y * 128 + wm + gid;
#pragma unroll
    for (int mt = 0; mt < 2; mt++) {
#pragma unroll
        for (int nt = 0; nt < 4; nt++) {
            int t0 = rbase + mt * 16;
            int d  = wn + nt * 8 + 2 * tig;
            *(float2*)(AV + ((size_t)b * Tv + t0) * HDv + h * Dv + d) =
                make_float2(acc[mt][nt][0], acc[mt][nt][1]);
            *(float2*)(AV + ((size_t)b * Tv + t0 + 8) * HDv + h * Dv + d) =
                make_float2(acc[mt][nt][2], acc[mt][nt][3]);
        }
    }
}

// ============================================================================
// Launch
// ============================================================================
extern "C" void kernel_launch(void* const* d_in, const int* in_sizes, int n_in,
                              void* d_out, int out_size)
{
    const float* q  = (const float*)d_in[0];
    const float* k  = (const float*)d_in[1];
    const float* v  = (const float*)d_in[2];
    const float* Wq = (const float*)d_in[3];
    const float* Wk = (const float*)d_in[4];
    const float* Wv = (const float*)d_in[5];
    const float* Wo = (const float*)d_in[6];

    float* xout    = (float*)d_out;                                        // [B,T,E]
    float* meanout = (float*)d_out + ((size_t)out_size - (size_t)Bv * Tv * Tv); // [B,T,T]

    float *pQ, *pK, *pV, *pS, *pM, *pL, *pAV;
    cudaGetSymbolAddress((void**)&pQ,  g_Q);
    cudaGetSymbolAddress((void**)&pK,  g_K);
    cudaGetSymbolAddress((void**)&pV,  g_V);
    cudaGetSymbolAddress((void**)&pS,  g_S);
    cudaGetSymbolAddress((void**)&pM,  g_M);
    cudaGetSymbolAddress((void**)&pL,  g_Linv);
    cudaGetSymbolAddress((void**)&pAV, g_AV);

    dim3 thr(128);

    // 1) Projections: [BT,E] @ W^T -> [b,h,t,d]
    dim3 gProj(HDv / 128, BTv / 128, 1);
    gemm_nt_h<1><<<gProj, thr>>>(q, Wq, pQ, BTv, HDv, Ev, 0, 0, 0, 1.0f);
    gemm_nt_h<1><<<gProj, thr>>>(k, Wk, pK, BTv, HDv, Ev, 0, 0, 0, 1.0f);
    gemm_nt_h<1><<<gProj, thr>>>(v, Wv, pV, BTv, HDv, Ev, 0, 0, 0, 1.0f);

    // 2) Scores: per (b,h), S = Q K^T / sqrt(D)
    dim3 gScore(Tv / 128, Tv / 128, BHv);
    gemm_nt_h<0><<<gScore, thr>>>(pQ, pK, pS, Tv, Tv, Dv,
                                  (size_t)Tv * Dv, (size_t)Tv * Dv,
                                  (size_t)Tv * Tv, 0.125f);

    // 3) Fused softmax stats + head-mean (reads S once, writes mean to d_out)
    stats_mean<<<BTv, 256>>>(pS, pM, pL, meanout);

    // 4) attn @ V with fused normalization -> g_AV [b,t,h*D]
    pv_gemm_h<<<dim3(1, Tv / 128, BHv), 256>>>(pS, pV, pM, pL, pAV);

    // 5) Output projection: [BT,HD] @ Wo^T -> x
    dim3 gOut(Ev / 128, BTv / 128, 1);
    gemm_nt_h<0><<<gOut, thr>>>(pAV, Wo, xout, BTv, Ev, HDv, 0, 0, 0, 1.0f);
}

// round 7
// speedup vs baseline: 2.5338x; 1.0572x over previous
#include <cuda_runtime.h>
#include <cuda_fp16.h>
#include <math.h>
#include <stdint.h>

// Problem constants
#define Bv  4
#define Tv  2048
#define Ev  1024
#define Hv  16
#define Dv  64
#define HDv 1024      // H*D
#define BTv 8192      // B*T
#define BHv 64        // B*H

// -------- scratch (device globals; no runtime allocation) --------
static __device__ float g_Q[(size_t)BHv * Tv * Dv];          // [b,h,t,d]
static __device__ float g_K[(size_t)BHv * Tv * Dv];
static __device__ float g_V[(size_t)BHv * Tv * Dv];
static __device__ float g_S[(size_t)BHv * Tv * Tv];          // raw scores (1 GiB)
static __device__ float g_M[BHv * Tv];                       // row max
static __device__ float g_Linv[BHv * Tv];                    // 1 / row sumexp
static __device__ float g_AV[(size_t)BTv * HDv];             // attn out, [b,t,h*D+d]

// ---------------- fp16 helpers ----------------
__device__ __forceinline__ uint32_t f2h2(float x, float y) {
    __half2 h = __floats2half2_rn(x, y);
    return *reinterpret_cast<uint32_t*>(&h);
}

// m16n8k16 fp16 mma, fp32 accumulate
__device__ __forceinline__ void mma_f16(float c[4],
        uint32_t a0, uint32_t a1, uint32_t a2, uint32_t a3,
        uint32_t b0, uint32_t b1)
{
    asm volatile(
        "mma.sync.aligned.m16n8k16.row.col.f32.f16.f16.f32 "
        "{%0,%1,%2,%3}, {%4,%5,%6,%7}, {%8,%9}, {%0,%1,%2,%3};"
        : "+f"(c[0]), "+f"(c[1]), "+f"(c[2]), "+f"(c[3])
        : "r"(a0), "r"(a1), "r"(a2), "r"(a3), "r"(b0), "r"(b1));
}

// Shared row pad: 16 k-pairs padded to 20 words -> 20*r mod 32 cycles
// {0,20,8,28,16,4,24,12}: conflict-free LDS fragments and uint4 STS.
#define KP 20

// ============================================================================
// fp16 tensor-core NT GEMM v3: C = alpha * A * B^T.  A:[M,K] ld=K, B:[N,K] ld=K.
// 128x128 block tile, 128 threads (4 warps 2Mx2N), warp tile 64x64,
// m16n8k16, BK=32, DOUBLE-BUFFERED shared with [row][k-pair] pad-20 layout.
// MODE 0: row-major C (ldc=N), batched via blockIdx.z strides, scaled by alpha
// MODE 1: projection store: row=(b,t), col=(h,d) -> C[((b*H+h)*T+t)*D+d]
// ============================================================================
template <int MODE>
__global__ void __launch_bounds__(128)
gemm_nt_h(const float* __restrict__ A, const float* __restrict__ Bm,
          float* __restrict__ C, int M, int N, int K,
          size_t sA, size_t sB, size_t sC, float alpha)
{
    __shared__ uint32_t As[2][128][KP];
    __shared__ uint32_t Bs[2][128][KP];

    const int tid  = threadIdx.x;
    const int lane = tid & 31;
    const int w    = tid >> 5;
    const int gid  = lane >> 2;     // 0..7
    const int tig  = lane & 3;      // 0..3
    const int wm   = (w & 1) * 64;
    const int wn   = (w >> 1) * 64;

    const float* Ab = A + blockIdx.z * sA + (size_t)(blockIdx.y * 128 + tid) * K;
    const float* Bb = Bm + blockIdx.z * sB + (size_t)(blockIdx.x * 128 + tid) * K;

    float acc[4][8][4];
#pragma unroll
    for (int mt = 0; mt < 4; mt++)
#pragma unroll
        for (int nt = 0; nt < 8; nt++)
#pragma unroll
            for (int i = 0; i < 4; i++) acc[mt][nt][i] = 0.0f;

    float4 pa[8], pb[8];
#pragma unroll
    for (int i = 0; i < 8; i++) {
        pa[i] = *(const float4*)(Ab + i * 4);
        pb[i] = *(const float4*)(Bb + i * 4);
    }
    // pack + store stage 0 into buf 0
#pragma unroll
    for (int i = 0; i < 2; i++) {
        *(uint4*)(&As[0][tid][8 * i]) = make_uint4(
            f2h2(pa[4*i+0].x, pa[4*i+0].y), f2h2(pa[4*i+0].z, pa[4*i+0].w),
            f2h2(pa[4*i+1].x, pa[4*i+1].y), f2h2(pa[4*i+1].z, pa[4*i+1].w));
        *(uint4*)(&As[0][tid][8 * i + 4]) = make_uint4(
            f2h2(pa[4*i+2].x, pa[4*i+2].y), f2h2(pa[4*i+2].z, pa[4*i+2].w),
            f2h2(pa[4*i+3].x, pa[4*i+3].y), f2h2(pa[4*i+3].z, pa[4*i+3].w));
        *(uint4*)(&Bs[0][tid][8 * i]) = make_uint4(
            f2h2(pb[4*i+0].x, pb[4*i+0].y), f2h2(pb[4*i+0].z, pb[4*i+0].w),
            f2h2(pb[4*i+1].x, pb[4*i+1].y), f2h2(pb[4*i+1].z, pb[4*i+1].w));
        *(uint4*)(&Bs[0][tid][8 * i + 4]) = make_uint4(
            f2h2(pb[4*i+2].x, pb[4*i+2].y), f2h2(pb[4*i+2].z, pb[4*i+2].w),
            f2h2(pb[4*i+3].x, pb[4*i+3].y), f2h2(pb[4*i+3].z, pb[4*i+3].w));
    }
    __syncthreads();

    const int nstages = K >> 5;
    for (int s = 0; s < nstages; s++) {
        const int cur = s & 1, nxt = cur ^ 1;
        const bool more = (s + 1) < nstages;
        if (more) {
            const int kn = (s + 1) * 32;
#pragma unroll
            for (int i = 0; i < 8; i++) {
                pa[i] = *(const float4*)(Ab + kn + i * 4);
                pb[i] = *(const float4*)(Bb + kn + i * 4);
            }
        }

#pragma unroll
        for (int ks = 0; ks < 16; ks += 8) {
            uint32_t bf[8][2];
#pragma unroll
            for (int nt = 0; nt < 8; nt++) {
                bf[nt][0] = Bs[cur][wn + nt * 8 + gid][ks + tig];
                bf[nt][1] = Bs[cur][wn + nt * 8 + gid][ks + tig + 4];
            }
#pragma unroll
            for (int mt = 0; mt < 4; mt++) {
                uint32_t a0 = As[cur][wm + mt * 16 + gid][ks + tig];
                uint32_t a1 = As[cur][wm + mt * 16 + gid + 8][ks + tig];
                uint32_t a2 = As[cur][wm + mt * 16 + gid][ks + tig + 4];
                uint32_t a3 = As[cur][wm + mt * 16 + gid + 8][ks + tig + 4];
#pragma unroll
                for (int nt = 0; nt < 8; nt++)
                    mma_f16(acc[mt][nt], a0, a1, a2, a3, bf[nt][0], bf[nt][1]);
            }
        }

        if (more) {
#pragma unroll
            for (int i = 0; i < 2; i++) {
                *(uint4*)(&As[nxt][tid][8 * i]) = make_uint4(
                    f2h2(pa[4*i+0].x, pa[4*i+0].y), f2h2(pa[4*i+0].z, pa[4*i+0].w),
                    f2h2(pa[4*i+1].x, pa[4*i+1].y), f2h2(pa[4*i+1].z, pa[4*i+1].w));
                *(uint4*)(&As[nxt][tid][8 * i + 4]) = make_uint4(
                    f2h2(pa[4*i+2].x, pa[4*i+2].y), f2h2(pa[4*i+2].z, pa[4*i+2].w),
                    f2h2(pa[4*i+3].x, pa[4*i+3].y), f2h2(pa[4*i+3].z, pa[4*i+3].w));
                *(uint4*)(&Bs[nxt][tid][8 * i]) = make_uint4(
                    f2h2(pb[4*i+0].x, pb[4*i+0].y), f2h2(pb[4*i+0].z, pb[4*i+0].w),
                    f2h2(pb[4*i+1].x, pb[4*i+1].y), f2h2(pb[4*i+1].z, pb[4*i+1].w));
                *(uint4*)(&Bs[nxt][tid][8 * i + 4]) = make_uint4(
                    f2h2(pb[4*i+2].x, pb[4*i+2].y), f2h2(pb[4*i+2].z, pb[4*i+2].w),
                    f2h2(pb[4*i+3].x, pb[4*i+3].y), f2h2(pb[4*i+3].z, pb[4*i+3].w));
            }
        }
        __syncthreads();
    }

    // ---- epilogue ----
    if (MODE == 0) {
        float* Cb = C + blockIdx.z * sC;
#pragma unroll
        for (int mt = 0; mt < 4; mt++) {
            const int r0 = blockIdx.y * 128 + wm + mt * 16 + gid;
#pragma unroll
            for (int nt = 0; nt < 8; nt++) {
                const int cc = blockIdx.x * 128 + wn + nt * 8 + 2 * tig;
                *(float2*)(&Cb[(size_t)r0 * N + cc]) =
                    make_float2(acc[mt][nt][0] * alpha, acc[mt][nt][1] * alpha);
                *(float2*)(&Cb[(size_t)(r0 + 8) * N + cc]) =
                    make_float2(acc[mt][nt][2] * alpha, acc[mt][nt][3] * alpha);
            }
        }
    } else {
#pragma unroll
        for (int mt = 0; mt < 4; mt++) {
            const int r0 = blockIdx.y * 128 + wm + mt * 16 + gid;
            const int b0 = r0 >> 11, t0 = r0 & 2047;
            const int r1 = r0 + 8;
            const int b1 = r1 >> 11, t1 = r1 & 2047;
#pragma unroll
            for (int nt = 0; nt < 8; nt++) {
                const int cc = blockIdx.x * 128 + wn + nt * 8 + 2 * tig;
                const int h = cc >> 6, d = cc & 63;
                *(float2*)(C + ((size_t)(b0 * Hv + h) * Tv + t0) * Dv + d) =
                    make_float2(acc[mt][nt][0], acc[mt][nt][1]);
                *(float2*)(C + ((size_t)(b1 * Hv + h) * Tv + t1) * Dv + d) =
                    make_float2(acc[mt][nt][2], acc[mt][nt][3]);
            }
        }
    }
}

// ============================================================================
// Fused softmax stats + head-mean output (unchanged).
// ============================================================================
__global__ void __launch_bounds__(256)
stats_mean(const float* __restrict__ S, float* __restrict__ Mv,
           float* __restrict__ Linv, float* __restrict__ meanout)
{
    const int bt   = blockIdx.x;
    const int b    = bt >> 11;
    const int t    = bt & 2047;
    const int tid  = threadIdx.x;
    const int lane = tid & 31;
    const int wid  = tid >> 5;

    __shared__ float red[8];

    float acc[8];
#pragma unroll
    for (int i = 0; i < 8; i++) acc[i] = 0.0f;

    for (int h = 0; h < Hv; h++) {
        const size_t base = ((size_t)(b * Hv + h) * Tv + t) * Tv;
        float v[8];
#pragma unroll
        for (int i = 0; i < 8; i++) v[i] = S[base + tid + i * 256];

        float m = v[0];
#pragma unroll
        for (int i = 1; i < 8; i++) m = fmaxf(m, v[i]);
#pragma unroll
        for (int o = 16; o > 0; o >>= 1)
            m = fmaxf(m, __shfl_xor_sync(0xffffffffu, m, o));
        if (lane == 0) red[wid] = m;
        __syncthreads();
        m = red[0];
#pragma unroll
        for (int i = 1; i < 8; i++) m = fmaxf(m, red[i]);

        float e[8];
        float l = 0.0f;
#pragma unroll
        for (int i = 0; i < 8; i++) { e[i] = __expf(v[i] - m); l += e[i]; }
#pragma unroll
        for (int o = 16; o > 0; o >>= 1)
            l += __shfl_xor_sync(0xffffffffu, l, o);
        __syncthreads();
        if (lane == 0) red[wid] = l;
        __syncthreads();
        l = red[0];
#pragma unroll
        for (int i = 1; i < 8; i++) l += red[i];
        const float linv = 1.0f / l;

        if (tid == 0) {
            Mv[(b * Hv + h) * Tv + t]   = m;
            Linv[(b * Hv + h) * Tv + t] = linv;
        }
#pragma unroll
        for (int i = 0; i < 8; i++) acc[i] += e[i] * linv;
        __syncthreads();
    }

    const size_t mb = (size_t)bt * Tv;
#pragma unroll
    for (int i = 0; i < 8; i++)
        meanout[mb + tid + i * 256] = acc[i] * (1.0f / Hv);
}

// ============================================================================
// P @ V fp16 GEMM v3: softmax fused into A loader; double-buffered, pad-20.
// 128x64 tile, 256 threads (8 warps, 4Mx2N), warp tile 32x32, BK=32.
// A loader: thread pair per row (16 floats each). B loader: thread = (d, pair
// group); coalesced LDG, conflict-free uint4 STS.
// ============================================================================
__global__ void __launch_bounds__(256)
pv_gemm_h(const float* __restrict__ S, const float* __restrict__ V,
          const float* __restrict__ Mv, const float* __restrict__ Linv,
          float* __restrict__ AV)
{
    __shared__ uint32_t As[2][128][KP];
    __shared__ uint32_t Bs[2][64][KP];

    const int tid  = threadIdx.x;
    const int lane = tid & 31;
    const int w    = tid >> 5;
    const int gid  = lane >> 2;
    const int tig  = lane & 3;
    const int wm   = (w & 3) * 32;
    const int wn   = (w >> 2) * 32;

    const int lrow = tid >> 1;          // 0..127: P row
    const int lph  = (tid & 1) * 8;     // pair offset 0 or 8 (=16 floats)
    const int bh   = blockIdx.z;

    const int arow   = blockIdx.y * 128 + lrow;
    const float mrow = Mv[bh * Tv + arow];
    const float lnv  = Linv[bh * Tv + arow];

    const float* Pb = S + (size_t)bh * Tv * Tv + (size_t)arow * Tv + lph * 2;
    const float* Vb = V + (size_t)bh * Tv * Dv;

    // V loader mapping: d = tid & 63, pair group g = tid >> 6 (pairs 4g..4g+3)
    const int vd = tid & 63;
    const int vg = tid >> 6;

    float acc[2][4][4];
#pragma unroll
    for (int mt = 0; mt < 2; mt++)
#pragma unroll
        for (int nt = 0; nt < 4; nt++)
#pragma unroll
            for (int i = 0; i < 4; i++) acc[mt][nt][i] = 0.0f;

    float4 av[4];
    float  bv[8];
#pragma unroll
    for (int i = 0; i < 4; i++) av[i] = *(const float4*)(Pb + i * 4);
#pragma unroll
    for (int j = 0; j < 8; j++) bv[j] = Vb[(size_t)(8 * vg + j) * Dv + vd];

    // pack + store stage 0
    {
        uint32_t u[8];
#pragma unroll
        for (int i = 0; i < 4; i++) {
            u[2*i]   = f2h2(__expf(av[i].x - mrow) * lnv, __expf(av[i].y - mrow) * lnv);
            u[2*i+1] = f2h2(__expf(av[i].z - mrow) * lnv, __expf(av[i].w - mrow) * lnv);
        }
        *(uint4*)(&As[0][lrow][lph])     = make_uint4(u[0], u[1], u[2], u[3]);
        *(uint4*)(&As[0][lrow][lph + 4]) = make_uint4(u[4], u[5], u[6], u[7]);
        *(uint4*)(&Bs[0][vd][4 * vg]) = make_uint4(
            f2h2(bv[0], bv[1]), f2h2(bv[2], bv[3]),
            f2h2(bv[4], bv[5]), f2h2(bv[6], bv[7]));
    }
    __syncthreads();

    const int nstages = Tv >> 5;   // 64
    for (int s = 0; s < nstages; s++) {
        const int cur = s & 1, nxt = cur ^ 1;
        const bool more = (s + 1) < nstages;
        if (more) {
            const int kn = (s + 1) * 32;
#pragma unroll
            for (int i = 0; i < 4; i++) av[i] = *(const float4*)(Pb + kn + i * 4);
#pragma unroll
            for (int j = 0; j < 8; j++)
                bv[j] = Vb[(size_t)(kn + 8 * vg + j) * Dv + vd];
        }

#pragma unroll
        for (int ks = 0; ks < 16; ks += 8) {
            uint32_t bf[4][2];
#pragma unroll
            for (int nt = 0; nt < 4; nt++) {
                bf[nt][0] = Bs[cur][wn + nt * 8 + gid][ks + tig];
                bf[nt][1] = Bs[cur][wn + nt * 8 + gid][ks + tig + 4];
            }
#pragma unroll
            for (int mt = 0; mt < 2; mt++) {
                uint32_t a0 = As[cur][wm + mt * 16 + gid][ks + tig];
                uint32_t a1 = As[cur][wm + mt * 16 + gid + 8][ks + tig];
                uint32_t a2 = As[cur][wm + mt * 16 + gid][ks + tig + 4];
                uint32_t a3 = As[cur][wm + mt * 16 + gid + 8][ks + tig + 4];
#pragma unroll
                for (int nt = 0; nt < 4; nt++)
                    mma_f16(acc[mt][nt], a0, a1, a2, a3, bf[nt][0], bf[nt][1]);
            }
        }

        if (more) {
            uint32_t u[8];
#pragma unroll
            for (int i = 0; i < 4; i++) {
                u[2*i]   = f2h2(__expf(av[i].x - mrow) * lnv, __expf(av[i].y - mrow) * lnv);
                u[2*i+1] = f2h2(__expf(av[i].z - mrow) * lnv, __expf(av[i].w - mrow) * lnv);
            }
            *(uint4*)(&As[nxt][lrow][lph])     = make_uint4(u[0], u[1], u[2], u[3]);
            *(uint4*)(&As[nxt][lrow][lph + 4]) = make_uint4(u[4], u[5], u[6], u[7]);
            *(uint4*)(&Bs[nxt][vd][4 * vg]) = make_uint4(
                f2h2(bv[0], bv[1]), f2h2(bv[2], bv[3]),
                f2h2(bv[4], bv[5]), f2h2(bv[6], bv[7]));
        }
        __syncthreads();
    }

    const int b = bh / Hv, h = bh % Hv;
    const int rbase = blockIdx.y * 128 + wm + gid;
#pragma unroll
    for (int mt = 0; mt < 2; mt++) {
#pragma unroll
        for (int nt = 0; nt < 4; nt++) {
            int t0 = rbase + mt * 16;
            int d  = wn + nt * 8 + 2 * tig;
            *(float2*)(AV + ((size_t)b * Tv + t0) * HDv + h * Dv + d) =
                make_float2(acc[mt][nt][0], acc[mt][nt][1]);
            *(float2*)(AV + ((size_t)b * Tv + t0 + 8) * HDv + h * Dv + d) =
                make_float2(acc[mt][nt][2], acc[mt][nt][3]);
        }
    }
}

// ============================================================================
// Launch
// ============================================================================
extern "C" void kernel_launch(void* const* d_in, const int* in_sizes, int n_in,
                              void* d_out, int out_size)
{
    const float* q  = (const float*)d_in[0];
    const float* k  = (const float*)d_in[1];
    const float* v  = (const float*)d_in[2];
    const float* Wq = (const float*)d_in[3];
    const float* Wk = (const float*)d_in[4];
    const float* Wv = (const float*)d_in[5];
    const float* Wo = (const float*)d_in[6];

    float* xout    = (float*)d_out;                                        // [B,T,E]
    float* meanout = (float*)d_out + ((size_t)out_size - (size_t)Bv * Tv * Tv); // [B,T,T]

    float *pQ, *pK, *pV, *pS, *pM, *pL, *pAV;
    cudaGetSymbolAddress((void**)&pQ,  g_Q);
    cudaGetSymbolAddress((void**)&pK,  g_K);
    cudaGetSymbolAddress((void**)&pV,  g_V);
    cudaGetSymbolAddress((void**)&pS,  g_S);
    cudaGetSymbolAddress((void**)&pM,  g_M);
    cudaGetSymbolAddress((void**)&pL,  g_Linv);
    cudaGetSymbolAddress((void**)&pAV, g_AV);

    dim3 thr(128);

    // 1) Projections: [BT,E] @ W^T -> [b,h,t,d]
    dim3 gProj(HDv / 128, BTv / 128, 1);
    gemm_nt_h<1><<<gProj, thr>>>(q, Wq, pQ, BTv, HDv, Ev, 0, 0, 0, 1.0f);
    gemm_nt_h<1><<<gProj, thr>>>(k, Wk, pK, BTv, HDv, Ev, 0, 0, 0, 1.0f);
    gemm_nt_h<1><<<gProj, thr>>>(v, Wv, pV, BTv, HDv, Ev, 0, 0, 0, 1.0f);

    // 2) Scores: per (b,h), S = Q K^T / sqrt(D)
    dim3 gScore(Tv / 128, Tv / 128, BHv);
    gemm_nt_h<0><<<gScore, thr>>>(pQ, pK, pS, Tv, Tv, Dv,
                                  (size_t)Tv * Dv, (size_t)Tv * Dv,
                                  (size_t)Tv * Tv, 0.125f);

    // 3) Fused softmax stats + head-mean (reads S once, writes mean to d_out)
    stats_mean<<<BTv, 256>>>(pS, pM, pL, meanout);

    // 4) attn @ V with fused normalization -> g_AV [b,t,h*D]
    pv_gemm_h<<<dim3(1, Tv / 128, BHv), 256>>>(pS, pV, pM, pL, pAV);

    // 5) Output projection: [BT,HD] @ Wo^T -> x
    dim3 gOut(Ev / 128, BTv / 128, 1);
    gemm_nt_h<0><<<gOut, thr>>>(pAV, Wo, xout, BTv, Ev, HDv, 0, 0, 0, 1.0f);
}